// round 13
// baseline (speedup 1.0000x reference)
#include <cuda_runtime.h>
#include <math.h>
#include <cstdint>

#define Bsz 128
#define Vsz 32000
#define Hsz 2048
#define Ssz 64
#define Lsz 2
#define NEGV -10000000000.0f

// ---------------- scratch (device globals) ----------------
__device__ float g_x0[Bsz * 4096];            // [emb, context]
__device__ float g_h0[Bsz * Hsz];
__device__ float g_h1[Bsz * Hsz];
__device__ float g_attx[Bsz * Hsz];           // reduced att_l1 result
__device__ float g_score[Ssz * Bsz];          // raw attention scores
__device__ float g_attn[Ssz * Bsz];
__device__ float g_cat2[Bsz * 4096];          // [ctx, hidden]
__device__ float g_out[Bsz * Hsz];            // tanh output (fc input)
__device__ float g_logits[(size_t)Bsz * Vsz];
__device__ float g_part[2 * Bsz * 8192];      // split-K partials (8 MB)

// ---------------- mma helpers ----------------
__device__ __forceinline__ uint32_t f2tf(float f) {
    uint32_t u; asm("cvt.rna.tf32.f32 %0, %1;" : "=r"(u) : "f"(f)); return u;
}
__device__ __forceinline__ void mma_tf32(float* c, const uint32_t* a, const uint32_t* b) {
    asm volatile("mma.sync.aligned.m16n8k8.row.col.f32.tf32.tf32.f32 "
        "{%0,%1,%2,%3}, {%4,%5,%6,%7}, {%8,%9}, {%0,%1,%2,%3};"
        : "+f"(c[0]), "+f"(c[1]), "+f"(c[2]), "+f"(c[3])
        : "r"(a[0]), "r"(a[1]), "r"(a[2]), "r"(a[3]), "r"(b[0]), "r"(b[1]));
}
__device__ __forceinline__ void mma_bf16(float* c, const uint32_t* a, const uint32_t* b) {
    asm volatile("mma.sync.aligned.m16n8k16.row.col.f32.bf16.bf16.f32 "
        "{%0,%1,%2,%3}, {%4,%5,%6,%7}, {%8,%9}, {%0,%1,%2,%3};"
        : "+f"(c[0]), "+f"(c[1]), "+f"(c[2]), "+f"(c[3])
        : "r"(a[0]), "r"(a[1]), "r"(a[2]), "r"(a[3]), "r"(b[0]), "r"(b[1]));
}
// pack (e0 even-k -> low half, e1 odd-k -> high half); hw = bf16 hi pair, lw = residual pair
__device__ __forceinline__ void split_pack(float e0, float e1, uint32_t& hw, uint32_t& lw) {
    uint32_t h; asm("cvt.rn.bf16x2.f32 %0, %1, %2;" : "=r"(h) : "f"(e1), "f"(e0));
    float h0 = __uint_as_float(h << 16);
    float h1 = __uint_as_float(h & 0xffff0000u);
    uint32_t l; asm("cvt.rn.bf16x2.f32 %0, %1, %2;" : "=r"(l) : "f"(e1 - h1), "f"(e0 - h0));
    hw = h; lw = l;
}

// ---------------- bf16x3 GEMM smem layout (proven) ----------------
#define AB_BLK 132
#define BB_BLK 66
#define AB_STG (16 * AB_BLK)
#define BB_STG (16 * BB_BLK)
#define SMEM_BF ((2 * (AB_STG + BB_STG)) * 2 * 4)   // 50688 bytes

__global__ void __launch_bounds__(256, 2) gemm_bf16(
    const float* __restrict__ A1, const float* __restrict__ W1, int K1,
    const float* __restrict__ A2, const float* __restrict__ W2, int K2,
    float* __restrict__ C, int ldc)
{
    extern __shared__ uint32_t smu[];
    uint32_t* Ah = smu;
    uint32_t* Al = Ah + 2 * AB_STG;
    uint32_t* Bh = Al + 2 * AB_STG;
    uint32_t* Bl = Bh + 2 * BB_STG;

    const int tid  = threadIdx.x;
    const int w    = tid >> 5, lane = tid & 31;
    const int wm   = w & 3,  wn = w >> 2;
    const int n0   = blockIdx.x * 64;
    const int g    = lane >> 2, tg = lane & 3;

    const int c4   = tid & 7;
    const int r0   = tid >> 3;
    const int kc16 = c4 >> 2;
    const int p0   = (2 * c4) & 7;

    int abase[4], bbase[2];
#pragma unroll
    for (int j = 0; j < 4; j++) {
        int r = r0 + 32 * j;
        int mb = r >> 4, r16 = r & 15;
        int slot = ((r16 >= 8) ? 1 : 0) + ((p0 >= 4) ? 2 : 0);
        abase[j] = (mb * 2 + kc16) * AB_BLK + ((r16 & 7) * 4 + (p0 & 3)) * 4 + slot;
    }
#pragma unroll
    for (int j = 0; j < 2; j++) {
        int r = r0 + 32 * j;
        int nb = r >> 3, cB = r & 7;
        bbase[j] = (nb * 2 + kc16) * BB_BLK + (cB * 4 + (p0 & 3)) * 2 + ((p0 >= 4) ? 1 : 0);
    }

    float acc[2][4][4];
#pragma unroll
    for (int i = 0; i < 2; i++)
#pragma unroll
        for (int jn = 0; jn < 4; jn++)
#pragma unroll
            for (int q = 0; q < 4; q++) acc[i][jn][q] = 0.f;

    const int T1 = K1 >> 5;
    const int T  = T1 + (K2 >> 5);
    const int tstart = (int)(((long long)T * blockIdx.y) / gridDim.y);
    const int tend   = (int)(((long long)T * (blockIdx.y + 1)) / gridDim.y);

    float4 ar[4], br[2];

    auto ldg_tile = [&](int t) {
        const float* Ap; const float* Wp; int K, k0;
        if (t < T1) { Ap = A1; Wp = W1; K = K1; k0 = t << 5; }
        else        { Ap = A2; Wp = W2; K = K2; k0 = (t - T1) << 5; }
        const float* ap = Ap + (size_t)r0 * K + k0 + c4 * 4;
        const float* wp = Wp + (size_t)(n0 + r0) * K + k0 + c4 * 4;
        const size_t step = (size_t)32 * K;
#pragma unroll
        for (int j = 0; j < 4; j++) ar[j] = *(const float4*)(ap + j * step);
#pragma unroll
        for (int j = 0; j < 2; j++) br[j] = *(const float4*)(wp + j * step);
    };
    auto sts_tile = [&](int s) {
        uint32_t* ah = Ah + s * AB_STG;
        uint32_t* al = Al + s * AB_STG;
        uint32_t* bh = Bh + s * BB_STG;
        uint32_t* bl = Bl + s * BB_STG;
        uint32_t hw, lw;
#pragma unroll
        for (int j = 0; j < 4; j++) {
            split_pack(ar[j].x, ar[j].y, hw, lw);
            ah[abase[j]] = hw;     al[abase[j]] = lw;
            split_pack(ar[j].z, ar[j].w, hw, lw);
            ah[abase[j] + 4] = hw; al[abase[j] + 4] = lw;
        }
#pragma unroll
        for (int j = 0; j < 2; j++) {
            split_pack(br[j].x, br[j].y, hw, lw);
            bh[bbase[j]] = hw;     bl[bbase[j]] = lw;
            split_pack(br[j].z, br[j].w, hw, lw);
            bh[bbase[j] + 2] = hw; bl[bbase[j] + 2] = lw;
        }
    };
    auto compute = [&](int s) {
        const uint32_t* ah = Ah + s * AB_STG;
        const uint32_t* al = Al + s * AB_STG;
        const uint32_t* bh = Bh + s * BB_STG;
        const uint32_t* bl = Bl + s * BB_STG;
#pragma unroll
        for (int kc = 0; kc < 2; kc++) {
            uint32_t bfh[4][2], bfl[4][2];
#pragma unroll
            for (int in_ = 0; in_ < 4; in_++) {
                int blkb = ((wn * 4 + in_) * 2 + kc) * BB_BLK;
                uint2 wv = *(const uint2*)(bh + blkb + lane * 2);
                bfh[in_][0] = wv.x; bfh[in_][1] = wv.y;
                uint2 wl = *(const uint2*)(bl + blkb + lane * 2);
                bfl[in_][0] = wl.x; bfl[in_][1] = wl.y;
            }
#pragma unroll
            for (int im = 0; im < 2; im++) {
                int blk = ((wm * 2 + im) * 2 + kc) * AB_BLK;
                uint32_t afh[4], afl[4];
                uint4 vh = *(const uint4*)(ah + blk + lane * 4);
                afh[0] = vh.x; afh[1] = vh.y; afh[2] = vh.z; afh[3] = vh.w;
                uint4 vl = *(const uint4*)(al + blk + lane * 4);
                afl[0] = vl.x; afl[1] = vl.y; afl[2] = vl.z; afl[3] = vl.w;
#pragma unroll
                for (int in_ = 0; in_ < 4; in_++) {
                    mma_bf16(acc[im][in_], afh, bfh[in_]);
                    mma_bf16(acc[im][in_], afh, bfl[in_]);
                    mma_bf16(acc[im][in_], afl, bfh[in_]);
                }
            }
        }
    };

    ldg_tile(tstart); sts_tile(0); __syncthreads();
    for (int t = tstart; t < tend; t++) {
        int s = (t - tstart) & 1;
        if (t + 1 < tend) ldg_tile(t + 1);
        compute(s);
        if (t + 1 < tend) sts_tile(s ^ 1);
        __syncthreads();
    }

    float* Cs = C + (size_t)blockIdx.y * 128 * ldc;
#pragma unroll
    for (int im = 0; im < 2; im++) {
        int mtop = wm * 32 + im * 16 + g;
#pragma unroll
        for (int in_ = 0; in_ < 4; in_++) {
            int nn = n0 + wn * 32 + in_ * 8 + tg * 2;
            *(float2*)&Cs[(size_t)mtop * ldc + nn] =
                make_float2(acc[im][in_][0], acc[im][in_][1]);
            *(float2*)&Cs[(size_t)(mtop + 8) * ldc + nn] =
                make_float2(acc[im][in_][2], acc[im][in_][3]);
        }
    }
}

// ---------------- tf32 single-pass GEMM (FC) ----------------
#define A_BLK 132
#define B_BLK 66
#define A_STG (8 * 4 * A_BLK)
#define B_STG (8 * 4 * B_BLK)
#define SMEM_LO  ((2 * A_STG + 2 * B_STG) * 4)

__global__ void __launch_bounds__(256, 2) gemm_tf32(
    const float* __restrict__ A1, const float* __restrict__ W1, int K1,
    float* __restrict__ C, int ldc)
{
    extern __shared__ uint32_t smu[];
    uint32_t* Ah = smu;
    uint32_t* Bh = smu + 2 * A_STG;

    const int tid  = threadIdx.x;
    const int w    = tid >> 5, lane = tid & 31;
    const int wm   = w & 3,  wn = w >> 2;
    const int n0   = blockIdx.x * 64;
    const int g    = lane >> 2, tg = lane & 3;

    const int c4 = tid & 7;
    const int r0 = tid >> 3;
    const int kc = c4 >> 1;
    const int hi = c4 & 1;

    int abase[4], bbase[2];
#pragma unroll
    for (int j = 0; j < 4; j++) {
        int row = r0 + 32 * j;
        int mb = row >> 4, r = row & 15;
        int slot = ((r < 8) ? 0 : 1) + (hi ? 2 : 0);
        abase[j] = (mb * 4 + kc) * A_BLK + (r & 7) * 16 + slot;
    }
#pragma unroll
    for (int j = 0; j < 2; j++) {
        int row = r0 + 32 * j;
        bbase[j] = ((row >> 3) * 4 + kc) * B_BLK + (row & 7) * 8 + hi;
    }

    float acc[2][4][4];
#pragma unroll
    for (int i = 0; i < 2; i++)
#pragma unroll
        for (int jn = 0; jn < 4; jn++)
#pragma unroll
            for (int q = 0; q < 4; q++) acc[i][jn][q] = 0.f;

    const int T = K1 >> 5;
    float4 ar[4], br[2];

    auto ldg_tile = [&](int t) {
        int k0 = t << 5;
        const float* ap = A1 + (size_t)r0 * K1 + k0 + c4 * 4;
        const float* wp = W1 + (size_t)(n0 + r0) * K1 + k0 + c4 * 4;
        const size_t step = (size_t)32 * K1;
#pragma unroll
        for (int j = 0; j < 4; j++) ar[j] = *(const float4*)(ap + j * step);
#pragma unroll
        for (int j = 0; j < 2; j++) br[j] = *(const float4*)(wp + j * step);
    };
    auto sts_tile = [&](int s) {
        uint32_t* a = Ah + s * A_STG;
        uint32_t* b = Bh + s * B_STG;
#pragma unroll
        for (int j = 0; j < 4; j++) {
            a[abase[j] + 0]  = f2tf(ar[j].x);
            a[abase[j] + 4]  = f2tf(ar[j].y);
            a[abase[j] + 8]  = f2tf(ar[j].z);
            a[abase[j] + 12] = f2tf(ar[j].w);
        }
#pragma unroll
        for (int j = 0; j < 2; j++) {
            b[bbase[j] + 0] = f2tf(br[j].x);
            b[bbase[j] + 2] = f2tf(br[j].y);
            b[bbase[j] + 4] = f2tf(br[j].z);
            b[bbase[j] + 6] = f2tf(br[j].w);
        }
    };
    auto compute = [&](int s) {
        const uint32_t* a_ = Ah + s * A_STG;
        const uint32_t* b_ = Bh + s * B_STG;
#pragma unroll
        for (int kk = 0; kk < 4; kk++) {
            uint32_t bf[4][2];
#pragma unroll
            for (int in_ = 0; in_ < 4; in_++) {
                uint2 wv = *(const uint2*)(b_ + ((wn * 4 + in_) * 4 + kk) * B_BLK + lane * 2);
                bf[in_][0] = wv.x; bf[in_][1] = wv.y;
            }
#pragma unroll
            for (int im = 0; im < 2; im++) {
                int mb = wm * 2 + im;
                uint32_t af[4];
                uint4 v = *(const uint4*)(a_ + (mb * 4 + kk) * A_BLK + lane * 4);
                af[0] = v.x; af[1] = v.y; af[2] = v.z; af[3] = v.w;
#pragma unroll
                for (int in_ = 0; in_ < 4; in_++)
                    mma_tf32(acc[im][in_], af, bf[in_]);
            }
        }
    };

    ldg_tile(0); sts_tile(0); __syncthreads();
    for (int t = 0; t < T; t++) {
        int s = t & 1;
        if (t + 1 < T) ldg_tile(t + 1);
        compute(s);
        if (t + 1 < T) sts_tile(s ^ 1);
        __syncthreads();
    }

#pragma unroll
    for (int im = 0; im < 2; im++) {
        int mtop = wm * 32 + im * 16 + g;
#pragma unroll
        for (int in_ = 0; in_ < 4; in_++) {
            int nn = n0 + wn * 32 + in_ * 8 + tg * 2;
            *(float2*)&C[(size_t)mtop * ldc + nn] =
                make_float2(acc[im][in_][0], acc[im][in_][1]);
            *(float2*)&C[(size_t)(mtop + 8) * ldc + nn] =
                make_float2(acc[im][in_][2], acc[im][in_][3]);
        }
    }
}

// ---------------- embedding gather + concat with context ----------------
__global__ void embed_concat(const int* __restrict__ dec,
                             const float* __restrict__ ctxv,
                             const float* __restrict__ emb)
{
    int idx = blockIdx.x * blockDim.x + threadIdx.x;
    if (idx >= Bsz * Hsz) return;
    int b = idx >> 11, e = idx & 2047;
    g_x0[(size_t)b * 4096 + e]        = emb[(size_t)dec[b] * Hsz + e];
    g_x0[(size_t)b * 4096 + 2048 + e] = ctxv[idx];
}

// ---------------- LSTM gate nonlinearity (sums 2 split-K slices) ----------------
__device__ __forceinline__ float sigf(float x) { return 1.f / (1.f + expf(-x)); }

__global__ void lstm_gate(const float* __restrict__ gp, int slice_stride,
                          const float* __restrict__ bih, const float* __restrict__ bhh,
                          const float* __restrict__ cprev,
                          float* __restrict__ cout,
                          float* __restrict__ hA, float* __restrict__ hB,
                          float* __restrict__ hC, int hCstride)
{
    int idx = blockIdx.x * blockDim.x + threadIdx.x;
    if (idx >= Bsz * Hsz) return;
    int b = idx >> 11;
    int j = idx & 2047;
    const float* g0 = gp + (size_t)b * 8192;
    const float* g1 = g0 + slice_stride;
    float gi = g0[j]        + g1[j]        + bih[j]        + bhh[j];
    float gf = g0[2048 + j] + g1[2048 + j] + bih[2048 + j] + bhh[2048 + j];
    float gc = g0[4096 + j] + g1[4096 + j] + bih[4096 + j] + bhh[4096 + j];
    float go = g0[6144 + j] + g1[6144 + j] + bih[6144 + j] + bhh[6144 + j];
    float c2 = sigf(gf) * cprev[idx] + sigf(gi) * tanhf(gc);
    float h2 = sigf(go) * tanhf(c2);
    cout[idx] = c2;
    hA[idx] = h2;
    hB[idx] = h2;
    if (hC) hC[(size_t)b * hCstride + j] = h2;
}

// ---------------- sum 8 split-K slices -> g_attx ----------------
__global__ void attx_reduce(const float* __restrict__ part)
{
    int idx = blockIdx.x * blockDim.x + threadIdx.x;
    if (idx >= Bsz * Hsz) return;
    const int SL = Bsz * Hsz;
    float v = part[idx];
#pragma unroll
    for (int y = 1; y < 8; y++) v += part[(size_t)y * SL + idx];
    g_attx[idx] = v;
}

// ---------------- raw scores: one warp per (b,s) ----------------
__global__ void __launch_bounds__(256) attn_score(const float* __restrict__ enc)
{
    int b = blockIdx.y;
    int w = threadIdx.x >> 5, lane = threadIdx.x & 31;
    int s = blockIdx.x * 8 + w;
    __shared__ float xs[2048];
    for (int k = threadIdx.x * 4; k < 2048; k += 1024)
        *(float4*)&xs[k] = *(const float4*)&g_attx[(size_t)b * 2048 + k];
    __syncthreads();
    const float* e = enc + ((size_t)b * Ssz + s) * 2048;
    float sum = 0.f;
    for (int k = lane * 4; k < 2048; k += 128) {
        float4 v = *(const float4*)&e[k];
        sum += v.x * xs[k] + v.y * xs[k + 1] + v.z * xs[k + 2] + v.w * xs[k + 3];
    }
#pragma unroll
    for (int o = 16; o > 0; o >>= 1) sum += __shfl_down_sync(0xffffffffu, sum, o);
    if (lane == 0) g_score[s * Bsz + b] = sum;
}

// ---------------- mask + softmax over S=64 (one block per b) ----------------
__global__ void __launch_bounds__(64) attn_soft(const int* __restrict__ slen,
                                                float* __restrict__ attn_out)
{
    int b = blockIdx.x;
    int t = threadIdx.x;
    __shared__ float sc[64];
    __shared__ float red[2];
    int len = slen[b];
    float v = (t < len) ? g_score[t * Bsz + b] : 0.f;
    if (v == 0.f) v = NEGV;
    sc[t] = v;
    __syncthreads();
    if (t == 0) {
        float m = -INFINITY;
        for (int s = 0; s < Ssz; s++) m = fmaxf(m, sc[s]);
        float ssum = 0.f;
        for (int s = 0; s < Ssz; s++) ssum += expf(sc[s] - m);
        red[0] = m; red[1] = ssum;
    }
    __syncthreads();
    float a = expf(sc[t] - red[0]) / red[1];
    attn_out[t * Bsz + b] = a;
    g_attn[t * Bsz + b] = a;
}

// ---------------- ctx: grid (2, B), 1024 h per block ----------------
__global__ void __launch_bounds__(256) ctx_kernel(const float* __restrict__ enc)
{
    int b = blockIdx.y;
    int h = blockIdx.x * 1024 + threadIdx.x * 4;
    __shared__ float at[Ssz];
    if (threadIdx.x < Ssz) at[threadIdx.x] = g_attn[threadIdx.x * Bsz + b];
    __syncthreads();
    float4 acc = make_float4(0.f, 0.f, 0.f, 0.f);
    const float* e = enc + (size_t)b * Ssz * 2048 + h;
#pragma unroll 4
    for (int s = 0; s < Ssz; s++) {
        float4 v = *(const float4*)&e[(size_t)s * 2048];
        float a = at[s];
        acc.x = fmaf(a, v.x, acc.x);
        acc.y = fmaf(a, v.y, acc.y);
        acc.z = fmaf(a, v.z, acc.z);
        acc.w = fmaf(a, v.w, acc.w);
    }
    *(float4*)&g_cat2[(size_t)b * 4096 + h] = acc;
}

// ---------------- tanh over sum of 8 split-K slices, dual destination ----------------
__global__ void tanh_red8(const float* __restrict__ part,
                          float* __restrict__ outA, float* __restrict__ outB)
{
    int idx = blockIdx.x * blockDim.x + threadIdx.x;
    if (idx >= Bsz * Hsz) return;
    const int SL = Bsz * Hsz;
    float v = part[idx];
#pragma unroll
    for (int y = 1; y < 8; y++) v += part[(size_t)y * SL + idx];
    v = tanhf(v);
    outA[idx] = v;
    outB[idx] = v;
}

// ---------------- log_softmax: online (m,s) single reduction + write pass ----------------
__global__ void __launch_bounds__(1024) logsoftmax_k(
    const float* __restrict__ fcb, float* __restrict__ outv)
{
    int b = blockIdx.x;
    const float* lg = g_logits + (size_t)b * Vsz;
    __shared__ float sm[32], ss[32];
    __shared__ float bc;
    const int tid = threadIdx.x;
    const int lane = tid & 31, warp = tid >> 5;

    float m = -INFINITY, s = 0.f;
    for (int n = tid; n < Vsz; n += 1024) {
        float x = lg[n] + fcb[n];
        if (x > m) { s = s * expf(m - x) + 1.f; m = x; }
        else       { s += expf(x - m); }
    }
#pragma unroll
    for (int o = 16; o > 0; o >>= 1) {
        float m2 = __shfl_down_sync(0xffffffffu, m, o);
        float s2 = __shfl_down_sync(0xffffffffu, s, o);
        float mn = fmaxf(m, m2);
        s = s * expf(m - mn) + s2 * expf(m2 - mn);
        m = mn;
    }
    if (lane == 0) { sm[warp] = m; ss[warp] = s; }
    __syncthreads();
    if (warp == 0) {
        float mv = sm[lane], sv = ss[lane];
#pragma unroll
        for (int o = 16; o > 0; o >>= 1) {
            float m2 = __shfl_down_sync(0xffffffffu, mv, o);
            float s2 = __shfl_down_sync(0xffffffffu, sv, o);
            float mn = fmaxf(mv, m2);
            sv = sv * expf(mv - mn) + s2 * expf(m2 - mn);
            mv = mn;
        }
        if (lane == 0) bc = mv + logf(sv);
    }
    __syncthreads();
    float lse = bc;
    for (int n = tid; n < Vsz; n += 1024)
        outv[(size_t)b * Vsz + n] = lg[n] + fcb[n] - lse;
}

// ---------------- launch ----------------
extern "C" void kernel_launch(void* const* d_in, const int* in_sizes, int n_in,
                              void* d_out, int out_size)
{
    const int*   dec  = (const int*)d_in[0];
    const float* ctxv = (const float*)d_in[1];
    const float* ph   = (const float*)d_in[2];   // (L,B,H)
    const float* pc   = (const float*)d_in[3];   // (L,B,H)
    const float* enc  = (const float*)d_in[4];   // (B,S,H)
    const int*   slen = (const int*)d_in[5];
    const float* emb  = (const float*)d_in[6];
    const float* Wih0 = (const float*)d_in[7];
    const float* Whh0 = (const float*)d_in[8];
    const float* bih0 = (const float*)d_in[9];
    const float* bhh0 = (const float*)d_in[10];
    const float* Wih1 = (const float*)d_in[11];
    const float* Whh1 = (const float*)d_in[12];
    const float* bih1 = (const float*)d_in[13];
    const float* bhh1 = (const float*)d_in[14];
    const float* al1  = (const float*)d_in[15];
    const float* al2  = (const float*)d_in[16];
    const float* fcw  = (const float*)d_in[17];
    const float* fcb  = (const float*)d_in[18];

    float* out       = (float*)d_out;
    float* out_vocab = out;                                   // B*V
    float* out_out   = out_vocab + (size_t)Bsz * Vsz;         // B*H
    float* out_h     = out_out + (size_t)Bsz * Hsz;           // L*B*H
    float* out_c     = out_h + (size_t)Lsz * Bsz * Hsz;       // L*B*H
    float* out_attn  = out_c + (size_t)Lsz * Bsz * Hsz;       // S*B

    float *px0, *ph0, *ph1, *pcat2, *pgout, *plog, *ppart;
    cudaGetSymbolAddress((void**)&px0,   g_x0);
    cudaGetSymbolAddress((void**)&ph0,   g_h0);
    cudaGetSymbolAddress((void**)&ph1,   g_h1);
    cudaGetSymbolAddress((void**)&pcat2, g_cat2);
    cudaGetSymbolAddress((void**)&pgout, g_out);
    cudaGetSymbolAddress((void**)&plog,  g_logits);
    cudaGetSymbolAddress((void**)&ppart, g_part);

    cudaFuncSetAttribute(gemm_bf16, cudaFuncAttributeMaxDynamicSharedMemorySize, SMEM_BF);
    cudaFuncSetAttribute(gemm_tf32, cudaFuncAttributeMaxDynamicSharedMemorySize, SMEM_LO);

    const int EW = (Bsz * Hsz + 255) / 256;
    const int LSL = Bsz * 8192;  // LSTM split-K slice stride (floats)

    // 1) x0 = [emb(dec), context]
    embed_concat<<<EW, 256>>>(dec, ctxv, emb);

    // 2) LSTM layer 0 (bf16x3, split-K x2)
    gemm_bf16<<<dim3(128, 2), 256, SMEM_BF>>>(px0, Wih0, 4096, ph, Whh0, 2048, ppart, 8192);
    lstm_gate<<<EW, 256>>>(ppart, LSL, bih0, bhh0, pc, out_c, ph0, out_h, nullptr, 0);

    // 3) LSTM layer 1 (bf16x3, split-K x2)
    gemm_bf16<<<dim3(128, 2), 256, SMEM_BF>>>(ph0, Wih1, 2048,
                                              ph + (size_t)Bsz * Hsz, Whh1, 2048, ppart, 8192);
    lstm_gate<<<EW, 256>>>(ppart, LSL, bih1, bhh1, pc + (size_t)Bsz * Hsz,
                           out_c + (size_t)Bsz * Hsz, ph1, out_h + (size_t)Bsz * Hsz,
                           pcat2 + 2048, 4096);

    // 4) attention: x = h1 @ att_l1^T (split-K x8), then wide-grid score/softmax/ctx
    gemm_bf16<<<dim3(32, 8), 256, SMEM_BF>>>(ph1, al1, 2048, nullptr, nullptr, 0, ppart, 2048);
    attx_reduce<<<EW, 256>>>(ppart);
    attn_score<<<dim3(8, Bsz), 256>>>(enc);
    attn_soft<<<Bsz, 64>>>(slen, out_attn);
    ctx_kernel<<<dim3(2, Bsz), 256>>>(enc);

    // 5) out = tanh([ctx, h1] @ att_l2^T)  (split-K x8)
    gemm_bf16<<<dim3(32, 8), 256, SMEM_BF>>>(pcat2, al2, 4096, nullptr, nullptr, 0, ppart, 2048);
    tanh_red8<<<EW, 256>>>(ppart, pgout, out_out);

    // 6) vocab logits + log_softmax
    gemm_tf32<<<dim3(500, 1), 256, SMEM_LO>>>(pgout, fcw, 2048, plog, 32000);
    logsoftmax_k<<<Bsz, 1024>>>(fcb, out_vocab);
}

// round 14
// speedup vs baseline: 1.4654x; 1.4654x over previous
#include <cuda_runtime.h>
#include <math.h>
#include <cstdint>

#define Bsz 128
#define Vsz 32000
#define Hsz 2048
#define Ssz 64
#define Lsz 2
#define NEGV -10000000000.0f

// ---------------- scratch (device globals) ----------------
__device__ float g_x0[Bsz * 4096];            // [emb, context]
__device__ float g_h0[Bsz * Hsz];
__device__ float g_h1[Bsz * Hsz];
__device__ float g_attn[Ssz * Bsz];
__device__ float g_cat2[Bsz * 4096];          // [ctx, hidden]
__device__ float g_out[Bsz * Hsz];            // tanh output (fc input)
__device__ float g_logits[(size_t)Bsz * Vsz];
__device__ float g_part[2 * Bsz * 8192];      // split-K partials (8 MB)

// ---------------- mma helpers ----------------
__device__ __forceinline__ uint32_t f2tf(float f) {
    uint32_t u; asm("cvt.rna.tf32.f32 %0, %1;" : "=r"(u) : "f"(f)); return u;
}
__device__ __forceinline__ void mma_tf32(float* c, const uint32_t* a, const uint32_t* b) {
    asm volatile("mma.sync.aligned.m16n8k8.row.col.f32.tf32.tf32.f32 "
        "{%0,%1,%2,%3}, {%4,%5,%6,%7}, {%8,%9}, {%0,%1,%2,%3};"
        : "+f"(c[0]), "+f"(c[1]), "+f"(c[2]), "+f"(c[3])
        : "r"(a[0]), "r"(a[1]), "r"(a[2]), "r"(a[3]), "r"(b[0]), "r"(b[1]));
}
__device__ __forceinline__ void mma_bf16(float* c, const uint32_t* a, const uint32_t* b) {
    asm volatile("mma.sync.aligned.m16n8k16.row.col.f32.bf16.bf16.f32 "
        "{%0,%1,%2,%3}, {%4,%5,%6,%7}, {%8,%9}, {%0,%1,%2,%3};"
        : "+f"(c[0]), "+f"(c[1]), "+f"(c[2]), "+f"(c[3])
        : "r"(a[0]), "r"(a[1]), "r"(a[2]), "r"(a[3]), "r"(b[0]), "r"(b[1]));
}
// pack (e0 even-k -> low half, e1 odd-k -> high half); hw = bf16 hi pair, lw = residual pair
__device__ __forceinline__ void split_pack(float e0, float e1, uint32_t& hw, uint32_t& lw) {
    uint32_t h; asm("cvt.rn.bf16x2.f32 %0, %1, %2;" : "=r"(h) : "f"(e1), "f"(e0));
    float h0 = __uint_as_float(h << 16);
    float h1 = __uint_as_float(h & 0xffff0000u);
    uint32_t l; asm("cvt.rn.bf16x2.f32 %0, %1, %2;" : "=r"(l) : "f"(e1 - h1), "f"(e0 - h0));
    hw = h; lw = l;
}

// ---------------- bf16x3 GEMM smem layout (proven round-10/12) ----------------
#define AB_BLK 132
#define BB_BLK 66
#define AB_STG (16 * AB_BLK)
#define BB_STG (16 * BB_BLK)
#define SMEM_BF ((2 * (AB_STG + BB_STG)) * 2 * 4)   // 50688 bytes

__global__ void __launch_bounds__(256, 2) gemm_bf16(
    const float* __restrict__ A1, const float* __restrict__ W1, int K1,
    const float* __restrict__ A2, const float* __restrict__ W2, int K2,
    float* __restrict__ C, int ldc)
{
    extern __shared__ uint32_t smu[];
    uint32_t* Ah = smu;
    uint32_t* Al = Ah + 2 * AB_STG;
    uint32_t* Bh = Al + 2 * AB_STG;
    uint32_t* Bl = Bh + 2 * BB_STG;

    const int tid  = threadIdx.x;
    const int w    = tid >> 5, lane = tid & 31;
    const int wm   = w & 3,  wn = w >> 2;
    const int n0   = blockIdx.x * 64;
    const int g    = lane >> 2, tg = lane & 3;

    const int c4   = tid & 7;
    const int r0   = tid >> 3;
    const int kc16 = c4 >> 2;
    const int p0   = (2 * c4) & 7;

    int abase[4], bbase[2];
#pragma unroll
    for (int j = 0; j < 4; j++) {
        int r = r0 + 32 * j;
        int mb = r >> 4, r16 = r & 15;
        int slot = ((r16 >= 8) ? 1 : 0) + ((p0 >= 4) ? 2 : 0);
        abase[j] = (mb * 2 + kc16) * AB_BLK + ((r16 & 7) * 4 + (p0 & 3)) * 4 + slot;
    }
#pragma unroll
    for (int j = 0; j < 2; j++) {
        int r = r0 + 32 * j;
        int nb = r >> 3, cB = r & 7;
        bbase[j] = (nb * 2 + kc16) * BB_BLK + (cB * 4 + (p0 & 3)) * 2 + ((p0 >= 4) ? 1 : 0);
    }

    float acc[2][4][4];
#pragma unroll
    for (int i = 0; i < 2; i++)
#pragma unroll
        for (int jn = 0; jn < 4; jn++)
#pragma unroll
            for (int q = 0; q < 4; q++) acc[i][jn][q] = 0.f;

    const int T1 = K1 >> 5;
    const int T  = T1 + (K2 >> 5);
    const int tstart = (int)(((long long)T * blockIdx.y) / gridDim.y);
    const int tend   = (int)(((long long)T * (blockIdx.y + 1)) / gridDim.y);

    float4 ar[4], br[2];

    auto ldg_tile = [&](int t) {
        const float* Ap; const float* Wp; int K, k0;
        if (t < T1) { Ap = A1; Wp = W1; K = K1; k0 = t << 5; }
        else        { Ap = A2; Wp = W2; K = K2; k0 = (t - T1) << 5; }
        const float* ap = Ap + (size_t)r0 * K + k0 + c4 * 4;
        const float* wp = Wp + (size_t)(n0 + r0) * K + k0 + c4 * 4;
        const size_t step = (size_t)32 * K;
#pragma unroll
        for (int j = 0; j < 4; j++) ar[j] = *(const float4*)(ap + j * step);
#pragma unroll
        for (int j = 0; j < 2; j++) br[j] = *(const float4*)(wp + j * step);
    };
    auto sts_tile = [&](int s) {
        uint32_t* ah = Ah + s * AB_STG;
        uint32_t* al = Al + s * AB_STG;
        uint32_t* bh = Bh + s * BB_STG;
        uint32_t* bl = Bl + s * BB_STG;
        uint32_t hw, lw;
#pragma unroll
        for (int j = 0; j < 4; j++) {
            split_pack(ar[j].x, ar[j].y, hw, lw);
            ah[abase[j]] = hw;     al[abase[j]] = lw;
            split_pack(ar[j].z, ar[j].w, hw, lw);
            ah[abase[j] + 4] = hw; al[abase[j] + 4] = lw;
        }
#pragma unroll
        for (int j = 0; j < 2; j++) {
            split_pack(br[j].x, br[j].y, hw, lw);
            bh[bbase[j]] = hw;     bl[bbase[j]] = lw;
            split_pack(br[j].z, br[j].w, hw, lw);
            bh[bbase[j] + 2] = hw; bl[bbase[j] + 2] = lw;
        }
    };
    auto compute = [&](int s) {
        const uint32_t* ah = Ah + s * AB_STG;
        const uint32_t* al = Al + s * AB_STG;
        const uint32_t* bh = Bh + s * BB_STG;
        const uint32_t* bl = Bl + s * BB_STG;
#pragma unroll
        for (int kc = 0; kc < 2; kc++) {
            uint32_t bfh[4][2], bfl[4][2];
#pragma unroll
            for (int in_ = 0; in_ < 4; in_++) {
                int blkb = ((wn * 4 + in_) * 2 + kc) * BB_BLK;
                uint2 wv = *(const uint2*)(bh + blkb + lane * 2);
                bfh[in_][0] = wv.x; bfh[in_][1] = wv.y;
                uint2 wl = *(const uint2*)(bl + blkb + lane * 2);
                bfl[in_][0] = wl.x; bfl[in_][1] = wl.y;
            }
#pragma unroll
            for (int im = 0; im < 2; im++) {
                int blk = ((wm * 2 + im) * 2 + kc) * AB_BLK;
                uint32_t afh[4], afl[4];
                uint4 vh = *(const uint4*)(ah + blk + lane * 4);
                afh[0] = vh.x; afh[1] = vh.y; afh[2] = vh.z; afh[3] = vh.w;
                uint4 vl = *(const uint4*)(al + blk + lane * 4);
                afl[0] = vl.x; afl[1] = vl.y; afl[2] = vl.z; afl[3] = vl.w;
#pragma unroll
                for (int in_ = 0; in_ < 4; in_++) {
                    mma_bf16(acc[im][in_], afh, bfh[in_]);
                    mma_bf16(acc[im][in_], afh, bfl[in_]);
                    mma_bf16(acc[im][in_], afl, bfh[in_]);
                }
            }
        }
    };

    ldg_tile(tstart); sts_tile(0); __syncthreads();
    for (int t = tstart; t < tend; t++) {
        int s = (t - tstart) & 1;
        if (t + 1 < tend) ldg_tile(t + 1);
        compute(s);
        if (t + 1 < tend) sts_tile(s ^ 1);
        __syncthreads();
    }

    float* Cs = C + (size_t)blockIdx.y * 128 * ldc;
#pragma unroll
    for (int im = 0; im < 2; im++) {
        int mtop = wm * 32 + im * 16 + g;
#pragma unroll
        for (int in_ = 0; in_ < 4; in_++) {
            int nn = n0 + wn * 32 + in_ * 8 + tg * 2;
            *(float2*)&Cs[(size_t)mtop * ldc + nn] =
                make_float2(acc[im][in_][0], acc[im][in_][1]);
            *(float2*)&Cs[(size_t)(mtop + 8) * ldc + nn] =
                make_float2(acc[im][in_][2], acc[im][in_][3]);
        }
    }
}

// ---------------- tf32 single-pass GEMM (FC) ----------------
#define A_BLK 132
#define B_BLK 66
#define A_STG (8 * 4 * A_BLK)
#define B_STG (8 * 4 * B_BLK)
#define SMEM_LO  ((2 * A_STG + 2 * B_STG) * 4)

__global__ void __launch_bounds__(256, 2) gemm_tf32(
    const float* __restrict__ A1, const float* __restrict__ W1, int K1,
    float* __restrict__ C, int ldc)
{
    extern __shared__ uint32_t smu[];
    uint32_t* Ah = smu;
    uint32_t* Bh = smu + 2 * A_STG;

    const int tid  = threadIdx.x;
    const int w    = tid >> 5, lane = tid & 31;
    const int wm   = w & 3,  wn = w >> 2;
    const int n0   = blockIdx.x * 64;
    const int g    = lane >> 2, tg = lane & 3;

    const int c4 = tid & 7;
    const int r0 = tid >> 3;
    const int kc = c4 >> 1;
    const int hi = c4 & 1;

    int abase[4], bbase[2];
#pragma unroll
    for (int j = 0; j < 4; j++) {
        int row = r0 + 32 * j;
        int mb = row >> 4, r = row & 15;
        int slot = ((r < 8) ? 0 : 1) + (hi ? 2 : 0);
        abase[j] = (mb * 4 + kc) * A_BLK + (r & 7) * 16 + slot;
    }
#pragma unroll
    for (int j = 0; j < 2; j++) {
        int row = r0 + 32 * j;
        bbase[j] = ((row >> 3) * 4 + kc) * B_BLK + (row & 7) * 8 + hi;
    }

    float acc[2][4][4];
#pragma unroll
    for (int i = 0; i < 2; i++)
#pragma unroll
        for (int jn = 0; jn < 4; jn++)
#pragma unroll
            for (int q = 0; q < 4; q++) acc[i][jn][q] = 0.f;

    const int T = K1 >> 5;
    float4 ar[4], br[2];

    auto ldg_tile = [&](int t) {
        int k0 = t << 5;
        const float* ap = A1 + (size_t)r0 * K1 + k0 + c4 * 4;
        const float* wp = W1 + (size_t)(n0 + r0) * K1 + k0 + c4 * 4;
        const size_t step = (size_t)32 * K1;
#pragma unroll
        for (int j = 0; j < 4; j++) ar[j] = *(const float4*)(ap + j * step);
#pragma unroll
        for (int j = 0; j < 2; j++) br[j] = *(const float4*)(wp + j * step);
    };
    auto sts_tile = [&](int s) {
        uint32_t* a = Ah + s * A_STG;
        uint32_t* b = Bh + s * B_STG;
#pragma unroll
        for (int j = 0; j < 4; j++) {
            a[abase[j] + 0]  = f2tf(ar[j].x);
            a[abase[j] + 4]  = f2tf(ar[j].y);
            a[abase[j] + 8]  = f2tf(ar[j].z);
            a[abase[j] + 12] = f2tf(ar[j].w);
        }
#pragma unroll
        for (int j = 0; j < 2; j++) {
            b[bbase[j] + 0] = f2tf(br[j].x);
            b[bbase[j] + 2] = f2tf(br[j].y);
            b[bbase[j] + 4] = f2tf(br[j].z);
            b[bbase[j] + 6] = f2tf(br[j].w);
        }
    };
    auto compute = [&](int s) {
        const uint32_t* a_ = Ah + s * A_STG;
        const uint32_t* b_ = Bh + s * B_STG;
#pragma unroll
        for (int kk = 0; kk < 4; kk++) {
            uint32_t bf[4][2];
#pragma unroll
            for (int in_ = 0; in_ < 4; in_++) {
                uint2 wv = *(const uint2*)(b_ + ((wn * 4 + in_) * 4 + kk) * B_BLK + lane * 2);
                bf[in_][0] = wv.x; bf[in_][1] = wv.y;
            }
#pragma unroll
            for (int im = 0; im < 2; im++) {
                int mb = wm * 2 + im;
                uint32_t af[4];
                uint4 v = *(const uint4*)(a_ + (mb * 4 + kk) * A_BLK + lane * 4);
                af[0] = v.x; af[1] = v.y; af[2] = v.z; af[3] = v.w;
#pragma unroll
                for (int in_ = 0; in_ < 4; in_++)
                    mma_tf32(acc[im][in_], af, bf[in_]);
            }
        }
    };

    ldg_tile(0); sts_tile(0); __syncthreads();
    for (int t = 0; t < T; t++) {
        int s = t & 1;
        if (t + 1 < T) ldg_tile(t + 1);
        compute(s);
        if (t + 1 < T) sts_tile(s ^ 1);
        __syncthreads();
    }

#pragma unroll
    for (int im = 0; im < 2; im++) {
        int mtop = wm * 32 + im * 16 + g;
#pragma unroll
        for (int in_ = 0; in_ < 4; in_++) {
            int nn = n0 + wn * 32 + in_ * 8 + tg * 2;
            *(float2*)&C[(size_t)mtop * ldc + nn] =
                make_float2(acc[im][in_][0], acc[im][in_][1]);
            *(float2*)&C[(size_t)(mtop + 8) * ldc + nn] =
                make_float2(acc[im][in_][2], acc[im][in_][3]);
        }
    }
}

// ---------------- embedding gather + concat with context ----------------
__global__ void embed_concat(const int* __restrict__ dec,
                             const float* __restrict__ ctxv,
                             const float* __restrict__ emb)
{
    int idx = blockIdx.x * blockDim.x + threadIdx.x;
    if (idx >= Bsz * Hsz) return;
    int b = idx >> 11, e = idx & 2047;
    g_x0[(size_t)b * 4096 + e]        = emb[(size_t)dec[b] * Hsz + e];
    g_x0[(size_t)b * 4096 + 2048 + e] = ctxv[idx];
}

// ---------------- LSTM gate nonlinearity (sums 2 split-K slices) ----------------
__device__ __forceinline__ float sigf(float x) { return 1.f / (1.f + expf(-x)); }

__global__ void lstm_gate(const float* __restrict__ gp, int slice_stride,
                          const float* __restrict__ bih, const float* __restrict__ bhh,
                          const float* __restrict__ cprev,
                          float* __restrict__ cout,
                          float* __restrict__ hA, float* __restrict__ hB,
                          float* __restrict__ hC, int hCstride)
{
    int idx = blockIdx.x * blockDim.x + threadIdx.x;
    if (idx >= Bsz * Hsz) return;
    int b = idx >> 11;
    int j = idx & 2047;
    const float* g0 = gp + (size_t)b * 8192;
    const float* g1 = g0 + slice_stride;
    float gi = g0[j]        + g1[j]        + bih[j]        + bhh[j];
    float gf = g0[2048 + j] + g1[2048 + j] + bih[2048 + j] + bhh[2048 + j];
    float gc = g0[4096 + j] + g1[4096 + j] + bih[4096 + j] + bhh[4096 + j];
    float go = g0[6144 + j] + g1[6144 + j] + bih[6144 + j] + bhh[6144 + j];
    float c2 = sigf(gf) * cprev[idx] + sigf(gi) * tanhf(gc);
    float h2 = sigf(go) * tanhf(c2);
    cout[idx] = c2;
    hA[idx] = h2;
    hB[idx] = h2;
    if (hC) hC[(size_t)b * hCstride + j] = h2;
}

// ---------------- attention: scores + mask + softmax + ctx (fused, sums 8 slices) ----------------
__global__ void __launch_bounds__(256) attn_softmax(
    const float* __restrict__ part,
    const float* __restrict__ enc, const int* __restrict__ slen,
    float* __restrict__ attn_out)
{
    int b = blockIdx.x;
    const int SL = Bsz * Hsz;   // 128*2048
    __shared__ float xs[2048];
    __shared__ float sc[64];
    __shared__ float at[64];
    __shared__ float red[2];
    for (int k = threadIdx.x * 4; k < 2048; k += 1024) {
        float4 s0 = *(const float4*)&part[(size_t)b * 2048 + k];
#pragma unroll
        for (int y = 1; y < 8; y++) {
            float4 v = *(const float4*)&part[(size_t)y * SL + b * 2048 + k];
            s0.x += v.x; s0.y += v.y; s0.z += v.z; s0.w += v.w;
        }
        xs[k] = s0.x; xs[k + 1] = s0.y; xs[k + 2] = s0.z; xs[k + 3] = s0.w;
    }
    __syncthreads();
    int warp = threadIdx.x >> 5, lane = threadIdx.x & 31;
    for (int s = warp; s < Ssz; s += 8) {
        const float* e = enc + ((size_t)b * Ssz + s) * 2048;
        float sum = 0.f;
        for (int k = lane * 4; k < 2048; k += 128) {
            float4 v = *(const float4*)&e[k];
            sum += v.x * xs[k] + v.y * xs[k + 1] + v.z * xs[k + 2] + v.w * xs[k + 3];
        }
#pragma unroll
        for (int o = 16; o > 0; o >>= 1) sum += __shfl_down_sync(0xffffffffu, sum, o);
        if (lane == 0) sc[s] = sum;
    }
    __syncthreads();
    int len = slen[b];
    if (threadIdx.x < Ssz) {
        float v = (threadIdx.x < len) ? sc[threadIdx.x] : 0.f;
        if (v == 0.f) v = NEGV;
        sc[threadIdx.x] = v;
    }
    __syncthreads();
    if (threadIdx.x == 0) {
        float m = -INFINITY;
        for (int s = 0; s < Ssz; s++) m = fmaxf(m, sc[s]);
        float ssum = 0.f;
        for (int s = 0; s < Ssz; s++) ssum += expf(sc[s] - m);
        red[0] = m; red[1] = ssum;
    }
    __syncthreads();
    if (threadIdx.x < Ssz) {
        float a = expf(sc[threadIdx.x] - red[0]) / red[1];
        attn_out[threadIdx.x * Bsz + b] = a;
        g_attn[threadIdx.x * Bsz + b] = a;
        at[threadIdx.x] = a;
    }
    __syncthreads();
    // fused ctx: ctx[b,h] = sum_s at[s] * enc[b,s,h] -> g_cat2[b][:2048]
    for (int h = threadIdx.x * 4; h < 2048; h += 1024) {
        float4 acc = make_float4(0.f, 0.f, 0.f, 0.f);
        const float* e = enc + (size_t)b * Ssz * 2048 + h;
#pragma unroll 4
        for (int s = 0; s < Ssz; s++) {
            float4 v = *(const float4*)&e[(size_t)s * 2048];
            float a = at[s];
            acc.x = fmaf(a, v.x, acc.x);
            acc.y = fmaf(a, v.y, acc.y);
            acc.z = fmaf(a, v.z, acc.z);
            acc.w = fmaf(a, v.w, acc.w);
        }
        *(float4*)&g_cat2[(size_t)b * 4096 + h] = acc;
    }
}

// ---------------- tanh over sum of 8 split-K slices, dual destination ----------------
__global__ void tanh_red8(const float* __restrict__ part,
                          float* __restrict__ outA, float* __restrict__ outB)
{
    int idx = blockIdx.x * blockDim.x + threadIdx.x;
    if (idx >= Bsz * Hsz) return;
    const int SL = Bsz * Hsz;
    float v = part[idx];
#pragma unroll
    for (int y = 1; y < 8; y++) v += part[(size_t)y * SL + idx];
    v = tanhf(v);
    outA[idx] = v;
    outB[idx] = v;
}

// ---------------- log_softmax: online (m,s) single reduction + write pass ----------------
__global__ void __launch_bounds__(1024) logsoftmax_k(
    const float* __restrict__ fcb, float* __restrict__ outv)
{
    int b = blockIdx.x;
    const float* lg = g_logits + (size_t)b * Vsz;
    __shared__ float sm[32], ss[32];
    __shared__ float bc;
    const int tid = threadIdx.x;
    const int lane = tid & 31, warp = tid >> 5;

    float m = -INFINITY, s = 0.f;
    for (int n = tid; n < Vsz; n += 1024) {
        float x = lg[n] + fcb[n];
        if (x > m) { s = s * expf(m - x) + 1.f; m = x; }
        else       { s += expf(x - m); }
    }
#pragma unroll
    for (int o = 16; o > 0; o >>= 1) {
        float m2 = __shfl_down_sync(0xffffffffu, m, o);
        float s2 = __shfl_down_sync(0xffffffffu, s, o);
        float mn = fmaxf(m, m2);
        s = s * expf(m - mn) + s2 * expf(m2 - mn);
        m = mn;
    }
    if (lane == 0) { sm[warp] = m; ss[warp] = s; }
    __syncthreads();
    if (warp == 0) {
        float mv = sm[lane], sv = ss[lane];
#pragma unroll
        for (int o = 16; o > 0; o >>= 1) {
            float m2 = __shfl_down_sync(0xffffffffu, mv, o);
            float s2 = __shfl_down_sync(0xffffffffu, sv, o);
            float mn = fmaxf(mv, m2);
            sv = sv * expf(mv - mn) + s2 * expf(m2 - mn);
            mv = mn;
        }
        if (lane == 0) bc = mv + logf(sv);
    }
    __syncthreads();
    float lse = bc;
    for (int n = tid; n < Vsz; n += 1024)
        outv[(size_t)b * Vsz + n] = lg[n] + fcb[n] - lse;
}

// ---------------- launch ----------------
extern "C" void kernel_launch(void* const* d_in, const int* in_sizes, int n_in,
                              void* d_out, int out_size)
{
    const int*   dec  = (const int*)d_in[0];
    const float* ctxv = (const float*)d_in[1];
    const float* ph   = (const float*)d_in[2];   // (L,B,H)
    const float* pc   = (const float*)d_in[3];   // (L,B,H)
    const float* enc  = (const float*)d_in[4];   // (B,S,H)
    const int*   slen = (const int*)d_in[5];
    const float* emb  = (const float*)d_in[6];
    const float* Wih0 = (const float*)d_in[7];
    const float* Whh0 = (const float*)d_in[8];
    const float* bih0 = (const float*)d_in[9];
    const float* bhh0 = (const float*)d_in[10];
    const float* Wih1 = (const float*)d_in[11];
    const float* Whh1 = (const float*)d_in[12];
    const float* bih1 = (const float*)d_in[13];
    const float* bhh1 = (const float*)d_in[14];
    const float* al1  = (const float*)d_in[15];
    const float* al2  = (const float*)d_in[16];
    const float* fcw  = (const float*)d_in[17];
    const float* fcb  = (const float*)d_in[18];

    float* out       = (float*)d_out;
    float* out_vocab = out;                                   // B*V
    float* out_out   = out_vocab + (size_t)Bsz * Vsz;         // B*H
    float* out_h     = out_out + (size_t)Bsz * Hsz;           // L*B*H
    float* out_c     = out_h + (size_t)Lsz * Bsz * Hsz;       // L*B*H
    float* out_attn  = out_c + (size_t)Lsz * Bsz * Hsz;       // S*B

    float *px0, *ph0, *ph1, *pcat2, *pgout, *plog, *ppart;
    cudaGetSymbolAddress((void**)&px0,   g_x0);
    cudaGetSymbolAddress((void**)&ph0,   g_h0);
    cudaGetSymbolAddress((void**)&ph1,   g_h1);
    cudaGetSymbolAddress((void**)&pcat2, g_cat2);
    cudaGetSymbolAddress((void**)&pgout, g_out);
    cudaGetSymbolAddress((void**)&plog,  g_logits);
    cudaGetSymbolAddress((void**)&ppart, g_part);

    cudaFuncSetAttribute(gemm_bf16, cudaFuncAttributeMaxDynamicSharedMemorySize, SMEM_BF);
    cudaFuncSetAttribute(gemm_tf32, cudaFuncAttributeMaxDynamicSharedMemorySize, SMEM_LO);

    const int EW = (Bsz * Hsz + 255) / 256;
    const int LSL = Bsz * 8192;  // LSTM split-K slice stride (floats)

    // 1) x0 = [emb(dec), context]
    embed_concat<<<EW, 256>>>(dec, ctxv, emb);

    // 2) LSTM layer 0: g = x0 @ Wih0^T + hprev0 @ Whh0^T  (bf16x3, split-K x2)
    gemm_bf16<<<dim3(128, 2), 256, SMEM_BF>>>(px0, Wih0, 4096, ph, Whh0, 2048, ppart, 8192);
    lstm_gate<<<EW, 256>>>(ppart, LSL, bih0, bhh0, pc, out_c, ph0, out_h, nullptr, 0);

    // 3) LSTM layer 1: g = h0 @ Wih1^T + hprev1 @ Whh1^T  (bf16x3, split-K x2)
    gemm_bf16<<<dim3(128, 2), 256, SMEM_BF>>>(ph0, Wih1, 2048,
                                              ph + (size_t)Bsz * Hsz, Whh1, 2048, ppart, 8192);
    lstm_gate<<<EW, 256>>>(ppart, LSL, bih1, bhh1, pc + (size_t)Bsz * Hsz,
                           out_c + (size_t)Bsz * Hsz, ph1, out_h + (size_t)Bsz * Hsz,
                           pcat2 + 2048, 4096);

    // 4) attention: x = h1 @ att_l1^T  (bf16x3, split-K x8; fused softmax+ctx)
    gemm_bf16<<<dim3(32, 8), 256, SMEM_BF>>>(ph1, al1, 2048, nullptr, nullptr, 0, ppart, 2048);
    attn_softmax<<<Bsz, 256>>>(ppart, enc, slen, out_attn);

    // 5) out = tanh([ctx, h1] @ att_l2^T)  (bf16x3, split-K x8; tanh sums slices)
    gemm_bf16<<<dim3(32, 8), 256, SMEM_BF>>>(pcat2, al2, 4096, nullptr, nullptr, 0, ppart, 2048);
    tanh_red8<<<EW, 256>>>(ppart, pgout, out_out);

    // 6) vocab logits + log_softmax (single tf32 — normalized downstream)
    gemm_tf32<<<dim3(500, 1), 256, SMEM_LO>>>(pgout, fcw, 2048, plog, 32000);
    logsoftmax_k<<<Bsz, 1024>>>(fcb, out_vocab);
}

// round 16
// speedup vs baseline: 1.5062x; 1.0278x over previous
#include <cuda_runtime.h>
#include <math.h>
#include <cstdint>

#define Bsz 128
#define Vsz 32000
#define Hsz 2048
#define Ssz 64
#define Lsz 2
#define NEGV -10000000000.0f

// ---------------- scratch (device globals) ----------------
__device__ float g_x0[Bsz * 4096];            // [emb, context]
__device__ float g_h0[Bsz * Hsz];
__device__ float g_h1[Bsz * Hsz];
__device__ float g_attn[Ssz * Bsz];
__device__ float g_cat2[Bsz * 4096];          // [ctx, hidden]
__device__ float g_out[Bsz * Hsz];            // tanh output (fc input)
__device__ float g_logits[(size_t)Bsz * Vsz];
__device__ float g_part[2 * Bsz * 8192];      // split-K partials (8 MB)

// ---------------- mma helpers ----------------
__device__ __forceinline__ void mma_bf16(float* c, const uint32_t* a, const uint32_t* b) {
    asm volatile("mma.sync.aligned.m16n8k16.row.col.f32.bf16.bf16.f32 "
        "{%0,%1,%2,%3}, {%4,%5,%6,%7}, {%8,%9}, {%0,%1,%2,%3};"
        : "+f"(c[0]), "+f"(c[1]), "+f"(c[2]), "+f"(c[3])
        : "r"(a[0]), "r"(a[1]), "r"(a[2]), "r"(a[3]), "r"(b[0]), "r"(b[1]));
}
// pack (e0 even-k -> low half, e1 odd-k -> high half); hw = bf16 hi pair, lw = residual pair
__device__ __forceinline__ void split_pack(float e0, float e1, uint32_t& hw, uint32_t& lw) {
    uint32_t h; asm("cvt.rn.bf16x2.f32 %0, %1, %2;" : "=r"(h) : "f"(e1), "f"(e0));
    float h0 = __uint_as_float(h << 16);
    float h1 = __uint_as_float(h & 0xffff0000u);
    uint32_t l; asm("cvt.rn.bf16x2.f32 %0, %1, %2;" : "=r"(l) : "f"(e1 - h1), "f"(e0 - h0));
    hw = h; lw = l;
}
__device__ __forceinline__ uint32_t pack_bf16(float e0, float e1) {
    uint32_t h; asm("cvt.rn.bf16x2.f32 %0, %1, %2;" : "=r"(h) : "f"(e1), "f"(e0));
    return h;
}

// ---------------- bf16x3 GEMM smem layout (proven round-10/12) ----------------
#define AB_BLK 132
#define BB_BLK 66
#define AB_STG (16 * AB_BLK)
#define BB_STG (16 * BB_BLK)
#define SMEM_BF ((2 * (AB_STG + BB_STG)) * 2 * 4)   // 50688 bytes

__global__ void __launch_bounds__(256, 2) gemm_bf16(
    const float* __restrict__ A1, const float* __restrict__ W1, int K1,
    const float* __restrict__ A2, const float* __restrict__ W2, int K2,
    float* __restrict__ C, int ldc)
{
    extern __shared__ uint32_t smu[];
    uint32_t* Ah = smu;
    uint32_t* Al = Ah + 2 * AB_STG;
    uint32_t* Bh = Al + 2 * AB_STG;
    uint32_t* Bl = Bh + 2 * BB_STG;

    const int tid  = threadIdx.x;
    const int w    = tid >> 5, lane = tid & 31;
    const int wm   = w & 3,  wn = w >> 2;
    const int n0   = blockIdx.x * 64;
    const int g    = lane >> 2, tg = lane & 3;

    const int c4   = tid & 7;
    const int r0   = tid >> 3;
    const int kc16 = c4 >> 2;
    const int p0   = (2 * c4) & 7;

    int abase[4], bbase[2];
#pragma unroll
    for (int j = 0; j < 4; j++) {
        int r = r0 + 32 * j;
        int mb = r >> 4, r16 = r & 15;
        int slot = ((r16 >= 8) ? 1 : 0) + ((p0 >= 4) ? 2 : 0);
        abase[j] = (mb * 2 + kc16) * AB_BLK + ((r16 & 7) * 4 + (p0 & 3)) * 4 + slot;
    }
#pragma unroll
    for (int j = 0; j < 2; j++) {
        int r = r0 + 32 * j;
        int nb = r >> 3, cB = r & 7;
        bbase[j] = (nb * 2 + kc16) * BB_BLK + (cB * 4 + (p0 & 3)) * 2 + ((p0 >= 4) ? 1 : 0);
    }

    float acc[2][4][4];
#pragma unroll
    for (int i = 0; i < 2; i++)
#pragma unroll
        for (int jn = 0; jn < 4; jn++)
#pragma unroll
            for (int q = 0; q < 4; q++) acc[i][jn][q] = 0.f;

    const int T1 = K1 >> 5;
    const int T  = T1 + (K2 >> 5);
    const int tstart = (int)(((long long)T * blockIdx.y) / gridDim.y);
    const int tend   = (int)(((long long)T * (blockIdx.y + 1)) / gridDim.y);

    float4 ar[4], br[2];

    auto ldg_tile = [&](int t) {
        const float* Ap; const float* Wp; int K, k0;
        if (t < T1) { Ap = A1; Wp = W1; K = K1; k0 = t << 5; }
        else        { Ap = A2; Wp = W2; K = K2; k0 = (t - T1) << 5; }
        const float* ap = Ap + (size_t)r0 * K + k0 + c4 * 4;
        const float* wp = Wp + (size_t)(n0 + r0) * K + k0 + c4 * 4;
        const size_t step = (size_t)32 * K;
#pragma unroll
        for (int j = 0; j < 4; j++) ar[j] = *(const float4*)(ap + j * step);
#pragma unroll
        for (int j = 0; j < 2; j++) br[j] = *(const float4*)(wp + j * step);
    };
    auto sts_tile = [&](int s) {
        uint32_t* ah = Ah + s * AB_STG;
        uint32_t* al = Al + s * AB_STG;
        uint32_t* bh = Bh + s * BB_STG;
        uint32_t* bl = Bl + s * BB_STG;
        uint32_t hw, lw;
#pragma unroll
        for (int j = 0; j < 4; j++) {
            split_pack(ar[j].x, ar[j].y, hw, lw);
            ah[abase[j]] = hw;     al[abase[j]] = lw;
            split_pack(ar[j].z, ar[j].w, hw, lw);
            ah[abase[j] + 4] = hw; al[abase[j] + 4] = lw;
        }
#pragma unroll
        for (int j = 0; j < 2; j++) {
            split_pack(br[j].x, br[j].y, hw, lw);
            bh[bbase[j]] = hw;     bl[bbase[j]] = lw;
            split_pack(br[j].z, br[j].w, hw, lw);
            bh[bbase[j] + 2] = hw; bl[bbase[j] + 2] = lw;
        }
    };
    auto compute = [&](int s) {
        const uint32_t* ah = Ah + s * AB_STG;
        const uint32_t* al = Al + s * AB_STG;
        const uint32_t* bh = Bh + s * BB_STG;
        const uint32_t* bl = Bl + s * BB_STG;
#pragma unroll
        for (int kc = 0; kc < 2; kc++) {
            uint32_t bfh[4][2], bfl[4][2];
#pragma unroll
            for (int in_ = 0; in_ < 4; in_++) {
                int blkb = ((wn * 4 + in_) * 2 + kc) * BB_BLK;
                uint2 wv = *(const uint2*)(bh + blkb + lane * 2);
                bfh[in_][0] = wv.x; bfh[in_][1] = wv.y;
                uint2 wl = *(const uint2*)(bl + blkb + lane * 2);
                bfl[in_][0] = wl.x; bfl[in_][1] = wl.y;
            }
#pragma unroll
            for (int im = 0; im < 2; im++) {
                int blk = ((wm * 2 + im) * 2 + kc) * AB_BLK;
                uint32_t afh[4], afl[4];
                uint4 vh = *(const uint4*)(ah + blk + lane * 4);
                afh[0] = vh.x; afh[1] = vh.y; afh[2] = vh.z; afh[3] = vh.w;
                uint4 vl = *(const uint4*)(al + blk + lane * 4);
                afl[0] = vl.x; afl[1] = vl.y; afl[2] = vl.z; afl[3] = vl.w;
#pragma unroll
                for (int in_ = 0; in_ < 4; in_++) {
                    mma_bf16(acc[im][in_], afh, bfh[in_]);
                    mma_bf16(acc[im][in_], afh, bfl[in_]);
                    mma_bf16(acc[im][in_], afl, bfh[in_]);
                }
            }
        }
    };

    ldg_tile(tstart); sts_tile(0); __syncthreads();
    for (int t = tstart; t < tend; t++) {
        int s = (t - tstart) & 1;
        if (t + 1 < tend) ldg_tile(t + 1);
        compute(s);
        if (t + 1 < tend) sts_tile(s ^ 1);
        __syncthreads();
    }

    float* Cs = C + (size_t)blockIdx.y * 128 * ldc;
#pragma unroll
    for (int im = 0; im < 2; im++) {
        int mtop = wm * 32 + im * 16 + g;
#pragma unroll
        for (int in_ = 0; in_ < 4; in_++) {
            int nn = n0 + wn * 32 + in_ * 8 + tg * 2;
            *(float2*)&Cs[(size_t)mtop * ldc + nn] =
                make_float2(acc[im][in_][0], acc[im][in_][1]);
            *(float2*)&Cs[(size_t)(mtop + 8) * ldc + nn] =
                make_float2(acc[im][in_][2], acc[im][in_][3]);
        }
    }
}

// ---------------- single-pass bf16 GEMM (FC logits; log-softmax normalized) ----------------
#define SMEM_FC ((2 * (AB_STG + BB_STG)) * 4)   // 25344 bytes (hi only, 2 stages)

__global__ void __launch_bounds__(256, 3) gemm_fc(
    const float* __restrict__ A1, const float* __restrict__ W1, int K1,
    float* __restrict__ C, int ldc)
{
    extern __shared__ uint32_t smu[];
    uint32_t* Ah = smu;                  // [2][AB_STG]
    uint32_t* Bh = Ah + 2 * AB_STG;      // [2][BB_STG]

    const int tid  = threadIdx.x;
    const int w    = tid >> 5, lane = tid & 31;
    const int wm   = w & 3,  wn = w >> 2;
    const int n0   = blockIdx.x * 64;
    const int g    = lane >> 2, tg = lane & 3;

    const int c4   = tid & 7;
    const int r0   = tid >> 3;
    const int kc16 = c4 >> 2;
    const int p0   = (2 * c4) & 7;

    int abase[4], bbase[2];
#pragma unroll
    for (int j = 0; j < 4; j++) {
        int r = r0 + 32 * j;
        int mb = r >> 4, r16 = r & 15;
        int slot = ((r16 >= 8) ? 1 : 0) + ((p0 >= 4) ? 2 : 0);
        abase[j] = (mb * 2 + kc16) * AB_BLK + ((r16 & 7) * 4 + (p0 & 3)) * 4 + slot;
    }
#pragma unroll
    for (int j = 0; j < 2; j++) {
        int r = r0 + 32 * j;
        int nb = r >> 3, cB = r & 7;
        bbase[j] = (nb * 2 + kc16) * BB_BLK + (cB * 4 + (p0 & 3)) * 2 + ((p0 >= 4) ? 1 : 0);
    }

    float acc[2][4][4];
#pragma unroll
    for (int i = 0; i < 2; i++)
#pragma unroll
        for (int jn = 0; jn < 4; jn++)
#pragma unroll
            for (int q = 0; q < 4; q++) acc[i][jn][q] = 0.f;

    const int T = K1 >> 5;
    float4 ar[4], br[2];

    auto ldg_tile = [&](int t) {
        int k0 = t << 5;
        const float* ap = A1 + (size_t)r0 * K1 + k0 + c4 * 4;
        const float* wp = W1 + (size_t)(n0 + r0) * K1 + k0 + c4 * 4;
        const size_t step = (size_t)32 * K1;
#pragma unroll
        for (int j = 0; j < 4; j++) ar[j] = *(const float4*)(ap + j * step);
#pragma unroll
        for (int j = 0; j < 2; j++) br[j] = *(const float4*)(wp + j * step);
    };
    auto sts_tile = [&](int s) {
        uint32_t* ah = Ah + s * AB_STG;
        uint32_t* bh = Bh + s * BB_STG;
#pragma unroll
        for (int j = 0; j < 4; j++) {
            ah[abase[j]]     = pack_bf16(ar[j].x, ar[j].y);
            ah[abase[j] + 4] = pack_bf16(ar[j].z, ar[j].w);
        }
#pragma unroll
        for (int j = 0; j < 2; j++) {
            bh[bbase[j]]     = pack_bf16(br[j].x, br[j].y);
            bh[bbase[j] + 2] = pack_bf16(br[j].z, br[j].w);
        }
    };
    auto compute = [&](int s) {
        const uint32_t* ah = Ah + s * AB_STG;
        const uint32_t* bh = Bh + s * BB_STG;
#pragma unroll
        for (int kc = 0; kc < 2; kc++) {
            uint32_t bfh[4][2];
#pragma unroll
            for (int in_ = 0; in_ < 4; in_++) {
                int blkb = ((wn * 4 + in_) * 2 + kc) * BB_BLK;
                uint2 wv = *(const uint2*)(bh + blkb + lane * 2);
                bfh[in_][0] = wv.x; bfh[in_][1] = wv.y;
            }
#pragma unroll
            for (int im = 0; im < 2; im++) {
                int blk = ((wm * 2 + im) * 2 + kc) * AB_BLK;
                uint32_t afh[4];
                uint4 vh = *(const uint4*)(ah + blk + lane * 4);
                afh[0] = vh.x; afh[1] = vh.y; afh[2] = vh.z; afh[3] = vh.w;
#pragma unroll
                for (int in_ = 0; in_ < 4; in_++)
                    mma_bf16(acc[im][in_], afh, bfh[in_]);
            }
        }
    };

    ldg_tile(0); sts_tile(0); __syncthreads();
    for (int t = 0; t < T; t++) {
        int s = t & 1;
        if (t + 1 < T) ldg_tile(t + 1);
        compute(s);
        if (t + 1 < T) sts_tile(s ^ 1);
        __syncthreads();
    }

#pragma unroll
    for (int im = 0; im < 2; im++) {
        int mtop = wm * 32 + im * 16 + g;
#pragma unroll
        for (int in_ = 0; in_ < 4; in_++) {
            int nn = n0 + wn * 32 + in_ * 8 + tg * 2;
            *(float2*)&C[(size_t)mtop * ldc + nn] =
                make_float2(acc[im][in_][0], acc[im][in_][1]);
            *(float2*)&C[(size_t)(mtop + 8) * ldc + nn] =
                make_float2(acc[im][in_][2], acc[im][in_][3]);
        }
    }
}

// ---------------- embedding gather + concat with context ----------------
__global__ void embed_concat(const int* __restrict__ dec,
                             const float* __restrict__ ctxv,
                             const float* __restrict__ emb)
{
    int idx = blockIdx.x * blockDim.x + threadIdx.x;
    if (idx >= Bsz * Hsz) return;
    int b = idx >> 11, e = idx & 2047;
    g_x0[(size_t)b * 4096 + e]        = emb[(size_t)dec[b] * Hsz + e];
    g_x0[(size_t)b * 4096 + 2048 + e] = ctxv[idx];
}

// ---------------- LSTM gate nonlinearity (sums 2 split-K slices) ----------------
__device__ __forceinline__ float sigf(float x) { return 1.f / (1.f + expf(-x)); }

__global__ void lstm_gate(const float* __restrict__ gp, int slice_stride,
                          const float* __restrict__ bih, const float* __restrict__ bhh,
                          const float* __restrict__ cprev,
                          float* __restrict__ cout,
                          float* __restrict__ hA, float* __restrict__ hB,
                          float* __restrict__ hC, int hCstride)
{
    int idx = blockIdx.x * blockDim.x + threadIdx.x;
    if (idx >= Bsz * Hsz) return;
    int b = idx >> 11;
    int j = idx & 2047;
    const float* g0 = gp + (size_t)b * 8192;
    const float* g1 = g0 + slice_stride;
    float gi = g0[j]        + g1[j]        + bih[j]        + bhh[j];
    float gf = g0[2048 + j] + g1[2048 + j] + bih[2048 + j] + bhh[2048 + j];
    float gc = g0[4096 + j] + g1[4096 + j] + bih[4096 + j] + bhh[4096 + j];
    float go = g0[6144 + j] + g1[6144 + j] + bih[6144 + j] + bhh[6144 + j];
    float c2 = sigf(gf) * cprev[idx] + sigf(gi) * tanhf(gc);
    float h2 = sigf(go) * tanhf(c2);
    cout[idx] = c2;
    hA[idx] = h2;
    hB[idx] = h2;
    if (hC) hC[(size_t)b * hCstride + j] = h2;
}

// ---------------- attention: scores + mask + softmax + ctx (fused, sums 8 slices) ----------------
__global__ void __launch_bounds__(256) attn_softmax(
    const float* __restrict__ part,
    const float* __restrict__ enc, const int* __restrict__ slen,
    float* __restrict__ attn_out)
{
    int b = blockIdx.x;
    const int SL = Bsz * Hsz;   // 128*2048
    __shared__ float xs[2048];
    __shared__ float sc[64];
    __shared__ float at[64];
    __shared__ float red[2];
    for (int k = threadIdx.x * 4; k < 2048; k += 1024) {
        float4 s0 = *(const float4*)&part[(size_t)b * 2048 + k];
#pragma unroll
        for (int y = 1; y < 8; y++) {
            float4 v = *(const float4*)&part[(size_t)y * SL + b * 2048 + k];
            s0.x += v.x; s0.y += v.y; s0.z += v.z; s0.w += v.w;
        }
        xs[k] = s0.x; xs[k + 1] = s0.y; xs[k + 2] = s0.z; xs[k + 3] = s0.w;
    }
    __syncthreads();
    int warp = threadIdx.x >> 5, lane = threadIdx.x & 31;
    for (int s = warp; s < Ssz; s += 8) {
        const float* e = enc + ((size_t)b * Ssz + s) * 2048;
        float sum = 0.f;
        for (int k = lane * 4; k < 2048; k += 128) {
            float4 v = *(const float4*)&e[k];
            sum += v.x * xs[k] + v.y * xs[k + 1] + v.z * xs[k + 2] + v.w * xs[k + 3];
        }
#pragma unroll
        for (int o = 16; o > 0; o >>= 1) sum += __shfl_down_sync(0xffffffffu, sum, o);
        if (lane == 0) sc[s] = sum;
    }
    __syncthreads();
    int len = slen[b];
    if (threadIdx.x < Ssz) {
        float v = (threadIdx.x < len) ? sc[threadIdx.x] : 0.f;
        if (v == 0.f) v = NEGV;
        sc[threadIdx.x] = v;
    }
    __syncthreads();
    if (threadIdx.x == 0) {
        float m = -INFINITY;
        for (int s = 0; s < Ssz; s++) m = fmaxf(m, sc[s]);
        float ssum = 0.f;
        for (int s = 0; s < Ssz; s++) ssum += expf(sc[s] - m);
        red[0] = m; red[1] = ssum;
    }
    __syncthreads();
    if (threadIdx.x < Ssz) {
        float a = expf(sc[threadIdx.x] - red[0]) / red[1];
        attn_out[threadIdx.x * Bsz + b] = a;
        g_attn[threadIdx.x * Bsz + b] = a;
        at[threadIdx.x] = a;
    }
    __syncthreads();
    // fused ctx: ctx[b,h] = sum_s at[s] * enc[b,s,h] -> g_cat2[b][:2048]
    for (int h = threadIdx.x * 4; h < 2048; h += 1024) {
        float4 acc = make_float4(0.f, 0.f, 0.f, 0.f);
        const float* e = enc + (size_t)b * Ssz * 2048 + h;
#pragma unroll 4
        for (int s = 0; s < Ssz; s++) {
            float4 v = *(const float4*)&e[(size_t)s * 2048];
            float a = at[s];
            acc.x = fmaf(a, v.x, acc.x);
            acc.y = fmaf(a, v.y, acc.y);
            acc.z = fmaf(a, v.z, acc.z);
            acc.w = fmaf(a, v.w, acc.w);
        }
        *(float4*)&g_cat2[(size_t)b * 4096 + h] = acc;
    }
}

// ---------------- tanh over sum of 8 split-K slices, dual destination ----------------
__global__ void tanh_red8(const float* __restrict__ part,
                          float* __restrict__ outA, float* __restrict__ outB)
{
    int idx = blockIdx.x * blockDim.x + threadIdx.x;
    if (idx >= Bsz * Hsz) return;
    const int SL = Bsz * Hsz;
    float v = part[idx];
#pragma unroll
    for (int y = 1; y < 8; y++) v += part[(size_t)y * SL + idx];
    v = tanhf(v);
    outA[idx] = v;
    outB[idx] = v;
}

// ---------------- log_softmax: online (m,s) single reduction + write pass ----------------
__global__ void __launch_bounds__(1024) logsoftmax_k(
    const float* __restrict__ fcb, float* __restrict__ outv)
{
    int b = blockIdx.x;
    const float* lg = g_logits + (size_t)b * Vsz;
    __shared__ float sm[32], ss[32];
    __shared__ float bc;
    const int tid = threadIdx.x;
    const int lane = tid & 31, warp = tid >> 5;

    float m = -INFINITY, s = 0.f;
    for (int n = tid; n < Vsz; n += 1024) {
        float x = lg[n] + fcb[n];
        if (x > m) { s = s * expf(m - x) + 1.f; m = x; }
        else       { s += expf(x - m); }
    }
#pragma unroll
    for (int o = 16; o > 0; o >>= 1) {
        float m2 = __shfl_down_sync(0xffffffffu, m, o);
        float s2 = __shfl_down_sync(0xffffffffu, s, o);
        float mn = fmaxf(m, m2);
        s = s * expf(m - mn) + s2 * expf(m2 - mn);
        m = mn;
    }
    if (lane == 0) { sm[warp] = m; ss[warp] = s; }
    __syncthreads();
    if (warp == 0) {
        float mv = sm[lane], sv = ss[lane];
#pragma unroll
        for (int o = 16; o > 0; o >>= 1) {
            float m2 = __shfl_down_sync(0xffffffffu, mv, o);
            float s2 = __shfl_down_sync(0xffffffffu, sv, o);
            float mn = fmaxf(mv, m2);
            sv = sv * expf(mv - mn) + s2 * expf(m2 - mn);
            mv = mn;
        }
        if (lane == 0) bc = mv + logf(sv);
    }
    __syncthreads();
    float lse = bc;
    for (int n = tid; n < Vsz; n += 1024)
        outv[(size_t)b * Vsz + n] = lg[n] + fcb[n] - lse;
}

// ---------------- launch ----------------
extern "C" void kernel_launch(void* const* d_in, const int* in_sizes, int n_in,
                              void* d_out, int out_size)
{
    const int*   dec  = (const int*)d_in[0];
    const float* ctxv = (const float*)d_in[1];
    const float* ph   = (const float*)d_in[2];   // (L,B,H)
    const float* pc   = (const float*)d_in[3];   // (L,B,H)
    const float* enc  = (const float*)d_in[4];   // (B,S,H)
    const int*   slen = (const int*)d_in[5];
    const float* emb  = (const float*)d_in[6];
    const float* Wih0 = (const float*)d_in[7];
    const float* Whh0 = (const float*)d_in[8];
    const float* bih0 = (const float*)d_in[9];
    const float* bhh0 = (const float*)d_in[10];
    const float* Wih1 = (const float*)d_in[11];
    const float* Whh1 = (const float*)d_in[12];
    const float* bih1 = (const float*)d_in[13];
    const float* bhh1 = (const float*)d_in[14];
    const float* al1  = (const float*)d_in[15];
    const float* al2  = (const float*)d_in[16];
    const float* fcw  = (const float*)d_in[17];
    const float* fcb  = (const float*)d_in[18];

    float* out       = (float*)d_out;
    float* out_vocab = out;                                   // B*V
    float* out_out   = out_vocab + (size_t)Bsz * Vsz;         // B*H
    float* out_h     = out_out + (size_t)Bsz * Hsz;           // L*B*H
    float* out_c     = out_h + (size_t)Lsz * Bsz * Hsz;       // L*B*H
    float* out_attn  = out_c + (size_t)Lsz * Bsz * Hsz;       // S*B

    float *px0, *ph0, *ph1, *pcat2, *pgout, *plog, *ppart;
    cudaGetSymbolAddress((void**)&px0,   g_x0);
    cudaGetSymbolAddress((void**)&ph0,   g_h0);
    cudaGetSymbolAddress((void**)&ph1,   g_h1);
    cudaGetSymbolAddress((void**)&pcat2, g_cat2);
    cudaGetSymbolAddress((void**)&pgout, g_out);
    cudaGetSymbolAddress((void**)&plog,  g_logits);
    cudaGetSymbolAddress((void**)&ppart, g_part);

    cudaFuncSetAttribute(gemm_bf16, cudaFuncAttributeMaxDynamicSharedMemorySize, SMEM_BF);
    cudaFuncSetAttribute(gemm_fc,   cudaFuncAttributeMaxDynamicSharedMemorySize, SMEM_FC);

    const int EW = (Bsz * Hsz + 255) / 256;
    const int LSL = Bsz * 8192;  // LSTM split-K slice stride (floats)

    // 1) x0 = [emb(dec), context]
    embed_concat<<<EW, 256>>>(dec, ctxv, emb);

    // 2) LSTM layer 0: g = x0 @ Wih0^T + hprev0 @ Whh0^T  (bf16x3, split-K x2)
    gemm_bf16<<<dim3(128, 2), 256, SMEM_BF>>>(px0, Wih0, 4096, ph, Whh0, 2048, ppart, 8192);
    lstm_gate<<<EW, 256>>>(ppart, LSL, bih0, bhh0, pc, out_c, ph0, out_h, nullptr, 0);

    // 3) LSTM layer 1: g = h0 @ Wih1^T + hprev1 @ Whh1^T  (bf16x3, split-K x2)
    gemm_bf16<<<dim3(128, 2), 256, SMEM_BF>>>(ph0, Wih1, 2048,
                                              ph + (size_t)Bsz * Hsz, Whh1, 2048, ppart, 8192);
    lstm_gate<<<EW, 256>>>(ppart, LSL, bih1, bhh1, pc + (size_t)Bsz * Hsz,
                           out_c + (size_t)Bsz * Hsz, ph1, out_h + (size_t)Bsz * Hsz,
                           pcat2 + 2048, 4096);

    // 4) attention: x = h1 @ att_l1^T  (bf16x3, split-K x8; fused softmax+ctx)
    gemm_bf16<<<dim3(32, 8), 256, SMEM_BF>>>(ph1, al1, 2048, nullptr, nullptr, 0, ppart, 2048);
    attn_softmax<<<Bsz, 256>>>(ppart, enc, slen, out_attn);

    // 5) out = tanh([ctx, h1] @ att_l2^T)  (bf16x3, split-K x8; tanh sums slices)
    gemm_bf16<<<dim3(32, 8), 256, SMEM_BF>>>(pcat2, al2, 4096, nullptr, nullptr, 0, ppart, 2048);
    tanh_red8<<<EW, 256>>>(ppart, pgout, out_out);

    // 6) vocab logits (single bf16 — normalized by log_softmax) + log_softmax
    gemm_fc<<<dim3(500, 1), 256, SMEM_FC>>>(pgout, fcw, 2048, plog, 32000);
    logsoftmax_k<<<Bsz, 1024>>>(fcb, out_vocab);
}

// round 17
// speedup vs baseline: 1.5497x; 1.0289x over previous
#include <cuda_runtime.h>
#include <math.h>
#include <cstdint>

#define Bsz 128
#define Vsz 32000
#define Hsz 2048
#define Ssz 64
#define Lsz 2
#define NEGV -10000000000.0f

// ---------------- scratch (device globals) ----------------
__device__ float g_x0[Bsz * 4096];            // [emb, context]
__device__ float g_h0[Bsz * Hsz];
__device__ float g_h1[Bsz * Hsz];
__device__ float g_attx[Bsz * Hsz];           // reduced att_l1 result
__device__ float g_score[Ssz * Bsz];          // raw attention scores
__device__ float g_attn[Ssz * Bsz];
__device__ float g_cat2[Bsz * 4096];          // [ctx, hidden]
__device__ float g_out[Bsz * Hsz];            // tanh output (fc input)
__device__ float g_logits[(size_t)Bsz * Vsz];
__device__ float g_part[2 * Bsz * 8192];      // split-K partials (8 MB)

// ---------------- mma helpers ----------------
__device__ __forceinline__ void mma_bf16(float* c, const uint32_t* a, const uint32_t* b) {
    asm volatile("mma.sync.aligned.m16n8k16.row.col.f32.bf16.bf16.f32 "
        "{%0,%1,%2,%3}, {%4,%5,%6,%7}, {%8,%9}, {%0,%1,%2,%3};"
        : "+f"(c[0]), "+f"(c[1]), "+f"(c[2]), "+f"(c[3])
        : "r"(a[0]), "r"(a[1]), "r"(a[2]), "r"(a[3]), "r"(b[0]), "r"(b[1]));
}
// pack (e0 even-k -> low half, e1 odd-k -> high half); hw = bf16 hi pair, lw = residual pair
__device__ __forceinline__ void split_pack(float e0, float e1, uint32_t& hw, uint32_t& lw) {
    uint32_t h; asm("cvt.rn.bf16x2.f32 %0, %1, %2;" : "=r"(h) : "f"(e1), "f"(e0));
    float h0 = __uint_as_float(h << 16);
    float h1 = __uint_as_float(h & 0xffff0000u);
    uint32_t l; asm("cvt.rn.bf16x2.f32 %0, %1, %2;" : "=r"(l) : "f"(e1 - h1), "f"(e0 - h0));
    hw = h; lw = l;
}
__device__ __forceinline__ uint32_t pack_bf16(float e0, float e1) {
    uint32_t h; asm("cvt.rn.bf16x2.f32 %0, %1, %2;" : "=r"(h) : "f"(e1), "f"(e0));
    return h;
}

// ---------------- bf16x3 GEMM smem layout (proven) ----------------
#define AB_BLK 132
#define BB_BLK 66
#define AB_STG (16 * AB_BLK)
#define BB_STG (16 * BB_BLK)
#define SMEM_BF ((2 * (AB_STG + BB_STG)) * 2 * 4)   // 50688 bytes

__global__ void __launch_bounds__(256, 2) gemm_bf16(
    const float* __restrict__ A1, const float* __restrict__ W1, int K1,
    const float* __restrict__ A2, const float* __restrict__ W2, int K2,
    float* __restrict__ C, int ldc)
{
    extern __shared__ uint32_t smu[];
    uint32_t* Ah = smu;
    uint32_t* Al = Ah + 2 * AB_STG;
    uint32_t* Bh = Al + 2 * AB_STG;
    uint32_t* Bl = Bh + 2 * BB_STG;

    const int tid  = threadIdx.x;
    const int w    = tid >> 5, lane = tid & 31;
    const int wm   = w & 3,  wn = w >> 2;
    const int n0   = blockIdx.x * 64;
    const int g    = lane >> 2, tg = lane & 3;

    const int c4   = tid & 7;
    const int r0   = tid >> 3;
    const int kc16 = c4 >> 2;
    const int p0   = (2 * c4) & 7;

    int abase[4], bbase[2];
#pragma unroll
    for (int j = 0; j < 4; j++) {
        int r = r0 + 32 * j;
        int mb = r >> 4, r16 = r & 15;
        int slot = ((r16 >= 8) ? 1 : 0) + ((p0 >= 4) ? 2 : 0);
        abase[j] = (mb * 2 + kc16) * AB_BLK + ((r16 & 7) * 4 + (p0 & 3)) * 4 + slot;
    }
#pragma unroll
    for (int j = 0; j < 2; j++) {
        int r = r0 + 32 * j;
        int nb = r >> 3, cB = r & 7;
        bbase[j] = (nb * 2 + kc16) * BB_BLK + (cB * 4 + (p0 & 3)) * 2 + ((p0 >= 4) ? 1 : 0);
    }

    float acc[2][4][4];
#pragma unroll
    for (int i = 0; i < 2; i++)
#pragma unroll
        for (int jn = 0; jn < 4; jn++)
#pragma unroll
            for (int q = 0; q < 4; q++) acc[i][jn][q] = 0.f;

    const int T1 = K1 >> 5;
    const int T  = T1 + (K2 >> 5);
    const int tstart = (int)(((long long)T * blockIdx.y) / gridDim.y);
    const int tend   = (int)(((long long)T * (blockIdx.y + 1)) / gridDim.y);

    float4 ar[4], br[2];

    auto ldg_tile = [&](int t) {
        const float* Ap; const float* Wp; int K, k0;
        if (t < T1) { Ap = A1; Wp = W1; K = K1; k0 = t << 5; }
        else        { Ap = A2; Wp = W2; K = K2; k0 = (t - T1) << 5; }
        const float* ap = Ap + (size_t)r0 * K + k0 + c4 * 4;
        const float* wp = Wp + (size_t)(n0 + r0) * K + k0 + c4 * 4;
        const size_t step = (size_t)32 * K;
#pragma unroll
        for (int j = 0; j < 4; j++) ar[j] = *(const float4*)(ap + j * step);
#pragma unroll
        for (int j = 0; j < 2; j++) br[j] = *(const float4*)(wp + j * step);
    };
    auto sts_tile = [&](int s) {
        uint32_t* ah = Ah + s * AB_STG;
        uint32_t* al = Al + s * AB_STG;
        uint32_t* bh = Bh + s * BB_STG;
        uint32_t* bl = Bl + s * BB_STG;
        uint32_t hw, lw;
#pragma unroll
        for (int j = 0; j < 4; j++) {
            split_pack(ar[j].x, ar[j].y, hw, lw);
            ah[abase[j]] = hw;     al[abase[j]] = lw;
            split_pack(ar[j].z, ar[j].w, hw, lw);
            ah[abase[j] + 4] = hw; al[abase[j] + 4] = lw;
        }
#pragma unroll
        for (int j = 0; j < 2; j++) {
            split_pack(br[j].x, br[j].y, hw, lw);
            bh[bbase[j]] = hw;     bl[bbase[j]] = lw;
            split_pack(br[j].z, br[j].w, hw, lw);
            bh[bbase[j] + 2] = hw; bl[bbase[j] + 2] = lw;
        }
    };
    auto compute = [&](int s) {
        const uint32_t* ah = Ah + s * AB_STG;
        const uint32_t* al = Al + s * AB_STG;
        const uint32_t* bh = Bh + s * BB_STG;
        const uint32_t* bl = Bl + s * BB_STG;
#pragma unroll
        for (int kc = 0; kc < 2; kc++) {
            uint32_t bfh[4][2], bfl[4][2];
#pragma unroll
            for (int in_ = 0; in_ < 4; in_++) {
                int blkb = ((wn * 4 + in_) * 2 + kc) * BB_BLK;
                uint2 wv = *(const uint2*)(bh + blkb + lane * 2);
                bfh[in_][0] = wv.x; bfh[in_][1] = wv.y;
                uint2 wl = *(const uint2*)(bl + blkb + lane * 2);
                bfl[in_][0] = wl.x; bfl[in_][1] = wl.y;
            }
#pragma unroll
            for (int im = 0; im < 2; im++) {
                int blk = ((wm * 2 + im) * 2 + kc) * AB_BLK;
                uint32_t afh[4], afl[4];
                uint4 vh = *(const uint4*)(ah + blk + lane * 4);
                afh[0] = vh.x; afh[1] = vh.y; afh[2] = vh.z; afh[3] = vh.w;
                uint4 vl = *(const uint4*)(al + blk + lane * 4);
                afl[0] = vl.x; afl[1] = vl.y; afl[2] = vl.z; afl[3] = vl.w;
#pragma unroll
                for (int in_ = 0; in_ < 4; in_++) {
                    mma_bf16(acc[im][in_], afh, bfh[in_]);
                    mma_bf16(acc[im][in_], afh, bfl[in_]);
                    mma_bf16(acc[im][in_], afl, bfh[in_]);
                }
            }
        }
    };

    ldg_tile(tstart); sts_tile(0); __syncthreads();
    for (int t = tstart; t < tend; t++) {
        int s = (t - tstart) & 1;
        if (t + 1 < tend) ldg_tile(t + 1);
        compute(s);
        if (t + 1 < tend) sts_tile(s ^ 1);
        __syncthreads();
    }

    float* Cs = C + (size_t)blockIdx.y * 128 * ldc;
#pragma unroll
    for (int im = 0; im < 2; im++) {
        int mtop = wm * 32 + im * 16 + g;
#pragma unroll
        for (int in_ = 0; in_ < 4; in_++) {
            int nn = n0 + wn * 32 + in_ * 8 + tg * 2;
            *(float2*)&Cs[(size_t)mtop * ldc + nn] =
                make_float2(acc[im][in_][0], acc[im][in_][1]);
            *(float2*)&Cs[(size_t)(mtop + 8) * ldc + nn] =
                make_float2(acc[im][in_][2], acc[im][in_][3]);
        }
    }
}

// ---------------- single-pass bf16 GEMM (FC logits; log-softmax normalized) ----------------
#define SMEM_FC ((2 * (AB_STG + BB_STG)) * 4)   // 25344 bytes (hi only, 2 stages)

__global__ void __launch_bounds__(256, 3) gemm_fc(
    const float* __restrict__ A1, const float* __restrict__ W1, int K1,
    float* __restrict__ C, int ldc)
{
    extern __shared__ uint32_t smu[];
    uint32_t* Ah = smu;                  // [2][AB_STG]
    uint32_t* Bh = Ah + 2 * AB_STG;      // [2][BB_STG]

    const int tid  = threadIdx.x;
    const int w    = tid >> 5, lane = tid & 31;
    const int wm   = w & 3,  wn = w >> 2;
    const int n0   = blockIdx.x * 64;
    const int g    = lane >> 2, tg = lane & 3;

    const int c4   = tid & 7;
    const int r0   = tid >> 3;
    const int kc16 = c4 >> 2;
    const int p0   = (2 * c4) & 7;

    int abase[4], bbase[2];
#pragma unroll
    for (int j = 0; j < 4; j++) {
        int r = r0 + 32 * j;
        int mb = r >> 4, r16 = r & 15;
        int slot = ((r16 >= 8) ? 1 : 0) + ((p0 >= 4) ? 2 : 0);
        abase[j] = (mb * 2 + kc16) * AB_BLK + ((r16 & 7) * 4 + (p0 & 3)) * 4 + slot;
    }
#pragma unroll
    for (int j = 0; j < 2; j++) {
        int r = r0 + 32 * j;
        int nb = r >> 3, cB = r & 7;
        bbase[j] = (nb * 2 + kc16) * BB_BLK + (cB * 4 + (p0 & 3)) * 2 + ((p0 >= 4) ? 1 : 0);
    }

    float acc[2][4][4];
#pragma unroll
    for (int i = 0; i < 2; i++)
#pragma unroll
        for (int jn = 0; jn < 4; jn++)
#pragma unroll
            for (int q = 0; q < 4; q++) acc[i][jn][q] = 0.f;

    const int T = K1 >> 5;
    float4 ar[4], br[2];

    auto ldg_tile = [&](int t) {
        int k0 = t << 5;
        const float* ap = A1 + (size_t)r0 * K1 + k0 + c4 * 4;
        const float* wp = W1 + (size_t)(n0 + r0) * K1 + k0 + c4 * 4;
        const size_t step = (size_t)32 * K1;
#pragma unroll
        for (int j = 0; j < 4; j++) ar[j] = *(const float4*)(ap + j * step);
#pragma unroll
        for (int j = 0; j < 2; j++) br[j] = *(const float4*)(wp + j * step);
    };
    auto sts_tile = [&](int s) {
        uint32_t* ah = Ah + s * AB_STG;
        uint32_t* bh = Bh + s * BB_STG;
#pragma unroll
        for (int j = 0; j < 4; j++) {
            ah[abase[j]]     = pack_bf16(ar[j].x, ar[j].y);
            ah[abase[j] + 4] = pack_bf16(ar[j].z, ar[j].w);
        }
#pragma unroll
        for (int j = 0; j < 2; j++) {
            bh[bbase[j]]     = pack_bf16(br[j].x, br[j].y);
            bh[bbase[j] + 2] = pack_bf16(br[j].z, br[j].w);
        }
    };
    auto compute = [&](int s) {
        const uint32_t* ah = Ah + s * AB_STG;
        const uint32_t* bh = Bh + s * BB_STG;
#pragma unroll
        for (int kc = 0; kc < 2; kc++) {
            uint32_t bfh[4][2];
#pragma unroll
            for (int in_ = 0; in_ < 4; in_++) {
                int blkb = ((wn * 4 + in_) * 2 + kc) * BB_BLK;
                uint2 wv = *(const uint2*)(bh + blkb + lane * 2);
                bfh[in_][0] = wv.x; bfh[in_][1] = wv.y;
            }
#pragma unroll
            for (int im = 0; im < 2; im++) {
                int blk = ((wm * 2 + im) * 2 + kc) * AB_BLK;
                uint32_t afh[4];
                uint4 vh = *(const uint4*)(ah + blk + lane * 4);
                afh[0] = vh.x; afh[1] = vh.y; afh[2] = vh.z; afh[3] = vh.w;
#pragma unroll
                for (int in_ = 0; in_ < 4; in_++)
                    mma_bf16(acc[im][in_], afh, bfh[in_]);
            }
        }
    };

    ldg_tile(0); sts_tile(0); __syncthreads();
    for (int t = 0; t < T; t++) {
        int s = t & 1;
        if (t + 1 < T) ldg_tile(t + 1);
        compute(s);
        if (t + 1 < T) sts_tile(s ^ 1);
        __syncthreads();
    }

#pragma unroll
    for (int im = 0; im < 2; im++) {
        int mtop = wm * 32 + im * 16 + g;
#pragma unroll
        for (int in_ = 0; in_ < 4; in_++) {
            int nn = n0 + wn * 32 + in_ * 8 + tg * 2;
            *(float2*)&C[(size_t)mtop * ldc + nn] =
                make_float2(acc[im][in_][0], acc[im][in_][1]);
            *(float2*)&C[(size_t)(mtop + 8) * ldc + nn] =
                make_float2(acc[im][in_][2], acc[im][in_][3]);
        }
    }
}

// ---------------- embedding gather + concat with context ----------------
__global__ void embed_concat(const int* __restrict__ dec,
                             const float* __restrict__ ctxv,
                             const float* __restrict__ emb)
{
    int idx = blockIdx.x * blockDim.x + threadIdx.x;
    if (idx >= Bsz * Hsz) return;
    int b = idx >> 11, e = idx & 2047;
    g_x0[(size_t)b * 4096 + e]        = emb[(size_t)dec[b] * Hsz + e];
    g_x0[(size_t)b * 4096 + 2048 + e] = ctxv[idx];
}

// ---------------- LSTM gate nonlinearity (sums 2 split-K slices) ----------------
__device__ __forceinline__ float sigf(float x) { return 1.f / (1.f + expf(-x)); }

__global__ void lstm_gate(const float* __restrict__ gp, int slice_stride,
                          const float* __restrict__ bih, const float* __restrict__ bhh,
                          const float* __restrict__ cprev,
                          float* __restrict__ cout,
                          float* __restrict__ hA, float* __restrict__ hB,
                          float* __restrict__ hC, int hCstride)
{
    int idx = blockIdx.x * blockDim.x + threadIdx.x;
    if (idx >= Bsz * Hsz) return;
    int b = idx >> 11;
    int j = idx & 2047;
    const float* g0 = gp + (size_t)b * 8192;
    const float* g1 = g0 + slice_stride;
    float gi = g0[j]        + g1[j]        + bih[j]        + bhh[j];
    float gf = g0[2048 + j] + g1[2048 + j] + bih[2048 + j] + bhh[2048 + j];
    float gc = g0[4096 + j] + g1[4096 + j] + bih[4096 + j] + bhh[4096 + j];
    float go = g0[6144 + j] + g1[6144 + j] + bih[6144 + j] + bhh[6144 + j];
    float c2 = sigf(gf) * cprev[idx] + sigf(gi) * tanhf(gc);
    float h2 = sigf(go) * tanhf(c2);
    cout[idx] = c2;
    hA[idx] = h2;
    hB[idx] = h2;
    if (hC) hC[(size_t)b * hCstride + j] = h2;
}

// ---------------- sum 8 split-K slices -> g_attx ----------------
__global__ void attx_reduce(const float* __restrict__ part)
{
    int idx = blockIdx.x * blockDim.x + threadIdx.x;
    if (idx >= Bsz * Hsz) return;
    const int SL = Bsz * Hsz;
    float v = part[idx];
#pragma unroll
    for (int y = 1; y < 8; y++) v += part[(size_t)y * SL + idx];
    g_attx[idx] = v;
}

// ---------------- raw scores: one warp per (b,s) ----------------
__global__ void __launch_bounds__(256) attn_score(const float* __restrict__ enc)
{
    int b = blockIdx.y;
    int w = threadIdx.x >> 5, lane = threadIdx.x & 31;
    int s = blockIdx.x * 8 + w;
    __shared__ float xs[2048];
    for (int k = threadIdx.x * 4; k < 2048; k += 1024)
        *(float4*)&xs[k] = *(const float4*)&g_attx[(size_t)b * 2048 + k];
    __syncthreads();
    const float* e = enc + ((size_t)b * Ssz + s) * 2048;
    float sum = 0.f;
    for (int k = lane * 4; k < 2048; k += 128) {
        float4 v = *(const float4*)&e[k];
        sum += v.x * xs[k] + v.y * xs[k + 1] + v.z * xs[k + 2] + v.w * xs[k + 3];
    }
#pragma unroll
    for (int o = 16; o > 0; o >>= 1) sum += __shfl_down_sync(0xffffffffu, sum, o);
    if (lane == 0) g_score[s * Bsz + b] = sum;
}

// ---------------- mask + softmax over S=64 (one block per b) ----------------
__global__ void __launch_bounds__(64) attn_soft(const int* __restrict__ slen,
                                                float* __restrict__ attn_out)
{
    int b = blockIdx.x;
    int t = threadIdx.x;
    __shared__ float sc[64];
    __shared__ float red[2];
    int len = slen[b];
    float v = (t < len) ? g_score[t * Bsz + b] : 0.f;
    if (v == 0.f) v = NEGV;
    sc[t] = v;
    __syncthreads();
    if (t == 0) {
        float m = -INFINITY;
        for (int s = 0; s < Ssz; s++) m = fmaxf(m, sc[s]);
        float ssum = 0.f;
        for (int s = 0; s < Ssz; s++) ssum += expf(sc[s] - m);
        red[0] = m; red[1] = ssum;
    }
    __syncthreads();
    float a = expf(sc[t] - red[0]) / red[1];
    attn_out[t * Bsz + b] = a;
    g_attn[t * Bsz + b] = a;
}

// ---------------- ctx: grid (2, B), 1024 h per block ----------------
__global__ void __launch_bounds__(256) ctx_kernel(const float* __restrict__ enc)
{
    int b = blockIdx.y;
    int h = blockIdx.x * 1024 + threadIdx.x * 4;
    __shared__ float at[Ssz];
    if (threadIdx.x < Ssz) at[threadIdx.x] = g_attn[threadIdx.x * Bsz + b];
    __syncthreads();
    float4 acc = make_float4(0.f, 0.f, 0.f, 0.f);
    const float* e = enc + (size_t)b * Ssz * 2048 + h;
#pragma unroll 4
    for (int s = 0; s < Ssz; s++) {
        float4 v = *(const float4*)&e[(size_t)s * 2048];
        float a = at[s];
        acc.x = fmaf(a, v.x, acc.x);
        acc.y = fmaf(a, v.y, acc.y);
        acc.z = fmaf(a, v.z, acc.z);
        acc.w = fmaf(a, v.w, acc.w);
    }
    *(float4*)&g_cat2[(size_t)b * 4096 + h] = acc;
}

// ---------------- tanh over sum of 8 split-K slices, dual destination ----------------
__global__ void tanh_red8(const float* __restrict__ part,
                          float* __restrict__ outA, float* __restrict__ outB)
{
    int idx = blockIdx.x * blockDim.x + threadIdx.x;
    if (idx >= Bsz * Hsz) return;
    const int SL = Bsz * Hsz;
    float v = part[idx];
#pragma unroll
    for (int y = 1; y < 8; y++) v += part[(size_t)y * SL + idx];
    v = tanhf(v);
    outA[idx] = v;
    outB[idx] = v;
}

// ---------------- log_softmax: online (m,s) single reduction + write pass ----------------
__global__ void __launch_bounds__(1024) logsoftmax_k(
    const float* __restrict__ fcb, float* __restrict__ outv)
{
    int b = blockIdx.x;
    const float* lg = g_logits + (size_t)b * Vsz;
    __shared__ float sm[32], ss[32];
    __shared__ float bc;
    const int tid = threadIdx.x;
    const int lane = tid & 31, warp = tid >> 5;

    float m = -INFINITY, s = 0.f;
    for (int n = tid; n < Vsz; n += 1024) {
        float x = lg[n] + fcb[n];
        if (x > m) { s = s * expf(m - x) + 1.f; m = x; }
        else       { s += expf(x - m); }
    }
#pragma unroll
    for (int o = 16; o > 0; o >>= 1) {
        float m2 = __shfl_down_sync(0xffffffffu, m, o);
        float s2 = __shfl_down_sync(0xffffffffu, s, o);
        float mn = fmaxf(m, m2);
        s = s * expf(m - mn) + s2 * expf(m2 - mn);
        m = mn;
    }
    if (lane == 0) { sm[warp] = m; ss[warp] = s; }
    __syncthreads();
    if (warp == 0) {
        float mv = sm[lane], sv = ss[lane];
#pragma unroll
        for (int o = 16; o > 0; o >>= 1) {
            float m2 = __shfl_down_sync(0xffffffffu, mv, o);
            float s2 = __shfl_down_sync(0xffffffffu, sv, o);
            float mn = fmaxf(mv, m2);
            sv = sv * expf(mv - mn) + s2 * expf(m2 - mn);
            mv = mn;
        }
        if (lane == 0) bc = mv + logf(sv);
    }
    __syncthreads();
    float lse = bc;
    for (int n = tid; n < Vsz; n += 1024)
        outv[(size_t)b * Vsz + n] = lg[n] + fcb[n] - lse;
}

// ---------------- launch ----------------
extern "C" void kernel_launch(void* const* d_in, const int* in_sizes, int n_in,
                              void* d_out, int out_size)
{
    const int*   dec  = (const int*)d_in[0];
    const float* ctxv = (const float*)d_in[1];
    const float* ph   = (const float*)d_in[2];   // (L,B,H)
    const float* pc   = (const float*)d_in[3];   // (L,B,H)
    const float* enc  = (const float*)d_in[4];   // (B,S,H)
    const int*   slen = (const int*)d_in[5];
    const float* emb  = (const float*)d_in[6];
    const float* Wih0 = (const float*)d_in[7];
    const float* Whh0 = (const float*)d_in[8];
    const float* bih0 = (const float*)d_in[9];
    const float* bhh0 = (const float*)d_in[10];
    const float* Wih1 = (const float*)d_in[11];
    const float* Whh1 = (const float*)d_in[12];
    const float* bih1 = (const float*)d_in[13];
    const float* bhh1 = (const float*)d_in[14];
    const float* al1  = (const float*)d_in[15];
    const float* al2  = (const float*)d_in[16];
    const float* fcw  = (const float*)d_in[17];
    const float* fcb  = (const float*)d_in[18];

    float* out       = (float*)d_out;
    float* out_vocab = out;                                   // B*V
    float* out_out   = out_vocab + (size_t)Bsz * Vsz;         // B*H
    float* out_h     = out_out + (size_t)Bsz * Hsz;           // L*B*H
    float* out_c     = out_h + (size_t)Lsz * Bsz * Hsz;       // L*B*H
    float* out_attn  = out_c + (size_t)Lsz * Bsz * Hsz;       // S*B

    float *px0, *ph0, *ph1, *pcat2, *pgout, *plog, *ppart;
    cudaGetSymbolAddress((void**)&px0,   g_x0);
    cudaGetSymbolAddress((void**)&ph0,   g_h0);
    cudaGetSymbolAddress((void**)&ph1,   g_h1);
    cudaGetSymbolAddress((void**)&pcat2, g_cat2);
    cudaGetSymbolAddress((void**)&pgout, g_out);
    cudaGetSymbolAddress((void**)&plog,  g_logits);
    cudaGetSymbolAddress((void**)&ppart, g_part);

    cudaFuncSetAttribute(gemm_bf16, cudaFuncAttributeMaxDynamicSharedMemorySize, SMEM_BF);
    cudaFuncSetAttribute(gemm_fc,   cudaFuncAttributeMaxDynamicSharedMemorySize, SMEM_FC);

    const int EW = (Bsz * Hsz + 255) / 256;
    const int LSL = Bsz * 8192;  // LSTM split-K slice stride (floats)

    // 1) x0 = [emb(dec), context]
    embed_concat<<<EW, 256>>>(dec, ctxv, emb);

    // 2) LSTM layer 0: g = x0 @ Wih0^T + hprev0 @ Whh0^T  (bf16x3, split-K x2)
    gemm_bf16<<<dim3(128, 2), 256, SMEM_BF>>>(px0, Wih0, 4096, ph, Whh0, 2048, ppart, 8192);
    lstm_gate<<<EW, 256>>>(ppart, LSL, bih0, bhh0, pc, out_c, ph0, out_h, nullptr, 0);

    // 3) LSTM layer 1: g = h0 @ Wih1^T + hprev1 @ Whh1^T  (bf16x3, split-K x2)
    gemm_bf16<<<dim3(128, 2), 256, SMEM_BF>>>(ph0, Wih1, 2048,
                                              ph + (size_t)Bsz * Hsz, Whh1, 2048, ppart, 8192);
    lstm_gate<<<EW, 256>>>(ppart, LSL, bih1, bhh1, pc + (size_t)Bsz * Hsz,
                           out_c + (size_t)Bsz * Hsz, ph1, out_h + (size_t)Bsz * Hsz,
                           pcat2 + 2048, 4096);

    // 4) attention: x = h1 @ att_l1^T (split-K x8), then wide-grid score/softmax/ctx
    gemm_bf16<<<dim3(32, 8), 256, SMEM_BF>>>(ph1, al1, 2048, nullptr, nullptr, 0, ppart, 2048);
    attx_reduce<<<EW, 256>>>(ppart);
    attn_score<<<dim3(8, Bsz), 256>>>(enc);
    attn_soft<<<Bsz, 64>>>(slen, out_attn);
    ctx_kernel<<<dim3(2, Bsz), 256>>>(enc);

    // 5) out = tanh([ctx, h1] @ att_l2^T)  (bf16x3, split-K x8)
    gemm_bf16<<<dim3(32, 8), 256, SMEM_BF>>>(pcat2, al2, 4096, nullptr, nullptr, 0, ppart, 2048);
    tanh_red8<<<EW, 256>>>(ppart, pgout, out_out);

    // 6) vocab logits (single bf16 — normalized by log_softmax) + log_softmax
    gemm_fc<<<dim3(500, 1), 256, SMEM_FC>>>(pgout, fcw, 2048, plog, 32000);
    logsoftmax_k<<<Bsz, 1024>>>(fcb, out_vocab);
}